// round 2
// baseline (speedup 1.0000x reference)
#include <cuda_runtime.h>
#include <math.h>
#include <stdint.h>

#define NCELLS 131072
#define RREG   512
#define DDIM   512
#define HDIM   256

typedef unsigned long long ull;

// ---------------- scratch (device globals; no allocations allowed) ----------
__device__ float g_w[NCELLS];               // own-region softmax prob (pass 1)
__device__ float g_m[RREG];                 // segment max of w
__device__ float g_denom[RREG];             // segment sum of exp(w-m)
__device__ float g_cnt[RREG];               // segment counts
__device__ float g_agg[RREG * HDIM];        // weighted segment sum of h
__device__ float g_upd[RREG * DDIM];        // updated_z_fused
__device__ float g_hb[RREG * HDIM];         // LN(GELU(upd @ w_d1))
__device__ float g_bcast[RREG * DDIM];      // down_broadcast

__device__ __forceinline__ float gelu_exact(float x) {
    return 0.5f * x * (1.0f + erff(x * 0.70710678118654752440f));
}
__device__ __forceinline__ ull pack2(float a) {
    ull r; asm("mov.b64 %0, {%1,%1};" : "=l"(r) : "f"(a)); return r;
}
__device__ __forceinline__ float2 unpack2(ull v) {
    float2 r; asm("mov.b64 {%0,%1}, %2;" : "=f"(r.x), "=f"(r.y) : "l"(v)); return r;
}
__device__ __forceinline__ void fma2(ull &d, ull a, ull b) {
    asm("fma.rn.f32x2 %0, %1, %2, %3;" : "=l"(d) : "l"(a), "l"(b), "l"(d));
}

// ---------------- init: zero per-call scratch --------------------------------
__global__ void init_kernel() {
    int i = blockIdx.x * blockDim.x + threadIdx.x;
    if (i < RREG * HDIM) g_agg[i] = 0.0f;
    if (i < RREG) { g_m[i] = 0.0f; g_denom[i] = 0.0f; g_cnt[i] = 0.0f; }
}

// ---------------- big pass GEMM + fused online softmax -----------------------
// scores[i,j] = dot(z_local[i], B[j]) / temp ; consume via online softmax.
// MODE 0: B = protos, writes g_w[i] = softmax prob of own region.
// MODE 1: B = g_upd,  writes out[i,:] = rw*bcast[reg[i],:]*w_i + (1-rw)*z[i,:]
#define TM 128
#define TN 128
#define TK 16
#define TMP 132   // padded strides (multiples of 4 floats, rows 16B-aligned)
#define TNP 132

template <int MODE>
__global__ __launch_bounds__(256) void pass_kernel(
    const float* __restrict__ A, const float* __restrict__ Bext,
    const int* __restrict__ regions, const float* __restrict__ temp,
    const float* __restrict__ raw_rw, float* __restrict__ out)
{
    __shared__ __align__(16) float As[TK][TMP];
    __shared__ __align__(16) float Bs[TK][TNP];
    __shared__ int   reg_s[TM];
    __shared__ float w_s[TM];

    const float* B = (MODE == 0) ? Bext : (const float*)g_upd;
    const int tid = threadIdx.x;
    const int tx = tid & 15;          // 16 col-groups of 8
    const int ty = tid >> 4;          // 16 row-groups of 8
    const int c0 = blockIdx.x * TM;
    const int R0 = ty * 8;
    const float inv_t = 1.0f / __ldg(temp);

    if (tid < TM) reg_s[tid] = regions[c0 + tid];

    float m_run[8], l_run[8], s_own[8];
#pragma unroll
    for (int r = 0; r < 8; r++) { m_run[r] = -3.4e38f; l_run[r] = 0.0f; s_own[r] = 0.0f; }

    for (int t = 0; t < RREG / TN; ++t) {
        const int col0 = t * TN;
        ull acc[8][4];   // acc[r][c] = rows R0+r, packed cols (col0+tx*8+2c, +1)
#pragma unroll
        for (int r = 0; r < 8; r++)
#pragma unroll
            for (int c = 0; c < 4; c++) acc[r][c] = 0ull;

        for (int k0 = 0; k0 < DDIM; k0 += TK) {
            __syncthreads();
#pragma unroll
            for (int p = 0; p < 2; ++p) {           // A tile 128x16, k-major
                int f = tid + p * 256;
                int row = f >> 2, seg = f & 3;
                float4 v = *reinterpret_cast<const float4*>(A + (size_t)(c0 + row) * DDIM + k0 + seg * 4);
                As[seg * 4 + 0][row] = v.x; As[seg * 4 + 1][row] = v.y;
                As[seg * 4 + 2][row] = v.z; As[seg * 4 + 3][row] = v.w;
            }
#pragma unroll
            for (int p = 0; p < 2; ++p) {           // B tile 128x16, k-major (transpose)
                int f = tid + p * 256;
                int j = f >> 2, seg = f & 3;
                float4 v = *reinterpret_cast<const float4*>(B + (size_t)(col0 + j) * DDIM + k0 + seg * 4);
                Bs[seg * 4 + 0][j] = v.x; Bs[seg * 4 + 1][j] = v.y;
                Bs[seg * 4 + 2][j] = v.z; Bs[seg * 4 + 3][j] = v.w;
            }
            __syncthreads();
#pragma unroll
            for (int kk = 0; kk < TK; ++kk) {
                float4 a0 = *reinterpret_cast<const float4*>(&As[kk][R0]);
                float4 a1 = *reinterpret_cast<const float4*>(&As[kk][R0 + 4]);
                ulonglong2 bq0 = *reinterpret_cast<const ulonglong2*>(&Bs[kk][tx * 8]);
                ulonglong2 bq1 = *reinterpret_cast<const ulonglong2*>(&Bs[kk][tx * 8 + 4]);
                ull ap[8] = { pack2(a0.x), pack2(a0.y), pack2(a0.z), pack2(a0.w),
                              pack2(a1.x), pack2(a1.y), pack2(a1.z), pack2(a1.w) };
                ull bb[4] = { bq0.x, bq0.y, bq1.x, bq1.y };
#pragma unroll
                for (int r = 0; r < 8; r++) {
                    fma2(acc[r][0], ap[r], bb[0]);
                    fma2(acc[r][1], ap[r], bb[1]);
                    fma2(acc[r][2], ap[r], bb[2]);
                    fma2(acc[r][3], ap[r], bb[3]);
                }
            }
        }
        // -------- online softmax update over this 128-col tile --------
#pragma unroll
        for (int rr = 0; rr < 8; ++rr) {
            float s[8];
#pragma unroll
            for (int c = 0; c < 4; c++) {
                float2 f = unpack2(acc[rr][c]);
                s[2 * c] = f.x * inv_t; s[2 * c + 1] = f.y * inv_t;
            }
            float tmax = s[0];
#pragma unroll
            for (int q = 1; q < 8; q++) tmax = fmaxf(tmax, s[q]);
#pragma unroll
            for (int off = 1; off < 16; off <<= 1)
                tmax = fmaxf(tmax, __shfl_xor_sync(0xffffffffu, tmax, off));
            float mo = m_run[rr];
            float mn = fmaxf(mo, tmax);
            float p = 0.0f;
#pragma unroll
            for (int q = 0; q < 8; q++) p += expf(s[q] - mn);
#pragma unroll
            for (int off = 1; off < 16; off <<= 1)
                p += __shfl_xor_sync(0xffffffffu, p, off);
            l_run[rr] = l_run[rr] * expf(mo - mn) + p;
            m_run[rr] = mn;
            int d = reg_s[R0 + rr] - col0;
            if ((unsigned)d < (unsigned)TN && (d >> 3) == tx) s_own[rr] += s[d & 7];
        }
    }
    // -------- finalize per-row own-region prob --------
#pragma unroll
    for (int rr = 0; rr < 8; ++rr) {
        float so = s_own[rr];
#pragma unroll
        for (int off = 1; off < 16; off <<= 1)
            so += __shfl_xor_sync(0xffffffffu, so, off);
        float wv = expf(so - m_run[rr]) / l_run[rr];
        if (tx == 0) {
            if (MODE == 0) g_w[c0 + R0 + rr] = wv;
            else           w_s[R0 + rr] = wv;
        }
    }
    if (MODE == 1) {
        __syncthreads();
        float xr = __ldg(raw_rw);
        float rw = 1.0f / (1.0f + expf(-xr));
        float orw = 1.0f - rw;
        for (int idx = tid; idx < TM * (DDIM / 4); idx += 256) {
            int row = idx >> 7;        // DDIM/4 = 128
            int c4 = idx & 127;
            int rg = reg_s[row];
            float wt = w_s[row];
            float4 bc = *reinterpret_cast<const float4*>(g_bcast + (size_t)rg * DDIM + c4 * 4);
            float4 zl = *reinterpret_cast<const float4*>(A + (size_t)(c0 + row) * DDIM + c4 * 4);
            float4 o;
            o.x = rw * (bc.x * wt) + orw * zl.x;
            o.y = rw * (bc.y * wt) + orw * zl.y;
            o.z = rw * (bc.z * wt) + orw * zl.z;
            o.w = rw * (bc.w * wt) + orw * zl.w;
            *reinterpret_cast<float4*>(out + (size_t)(c0 + row) * DDIM + c4 * 4) = o;
        }
    }
}

// ---------------- segment max / sum over w -----------------------------------
__global__ void seg_max_kernel(const int* __restrict__ regions) {
    int i = blockIdx.x * blockDim.x + threadIdx.x;
    if (i < NCELLS)  // w > 0 always, so int-compare trick is valid with init 0
        atomicMax((int*)&g_m[regions[i]], __float_as_int(g_w[i]));
}
__global__ void seg_sum_kernel(const int* __restrict__ regions) {
    int i = blockIdx.x * blockDim.x + threadIdx.x;
    if (i < NCELLS) {
        int r = regions[i];
        float e = expf(g_w[i] - g_m[r]);
        atomicAdd(&g_denom[r], e);
        atomicAdd(&g_cnt[r], 1.0f);
    }
}

// ---------------- h = LN(GELU(z @ w_ua + b_ua)); agg += h * w_norm -----------
#define HM 64
__global__ __launch_bounds__(256) void h_agg_kernel(
    const float* __restrict__ A, const float* __restrict__ w_ua,
    const float* __restrict__ b_ua, const float* __restrict__ g_ua,
    const float* __restrict__ be_ua, const int* __restrict__ regions)
{
    __shared__ __align__(16) float As[TK][68];     // 64+4, rows 16B aligned
    __shared__ __align__(16) float Bs[TK][260];    // 256+4

    const int tid = threadIdx.x;
    const int tx = tid & 31;          // 32 col-groups of 8 (covers H=256)
    const int ty = tid >> 5;          // 8 row-groups of 8 (covers 64 rows)
    const int c0 = blockIdx.x * HM;
    const int R0 = ty * 8;
    const int C0 = tx * 8;

    ull acc[8][4];
#pragma unroll
    for (int r = 0; r < 8; r++)
#pragma unroll
        for (int c = 0; c < 4; c++) acc[r][c] = 0ull;

    for (int k0 = 0; k0 < DDIM; k0 += TK) {
        __syncthreads();
        {   // A tile 64x16 (transpose to k-major)
            int row = tid >> 2, seg = tid & 3;
            float4 v = *reinterpret_cast<const float4*>(A + (size_t)(c0 + row) * DDIM + k0 + seg * 4);
            As[seg * 4 + 0][row] = v.x; As[seg * 4 + 1][row] = v.y;
            As[seg * 4 + 2][row] = v.z; As[seg * 4 + 3][row] = v.w;
        }
#pragma unroll
        for (int p = 0; p < 4; ++p) {   // B tile 16x256 (already k-major in w_ua)
            int f = tid + p * 256;
            int k = f >> 6, c4 = f & 63;
            float4 v = *reinterpret_cast<const float4*>(w_ua + (size_t)(k0 + k) * HDIM + c4 * 4);
            *reinterpret_cast<float4*>(&Bs[k][c4 * 4]) = v;
        }
        __syncthreads();
#pragma unroll
        for (int kk = 0; kk < TK; ++kk) {
            float4 a0 = *reinterpret_cast<const float4*>(&As[kk][R0]);
            float4 a1 = *reinterpret_cast<const float4*>(&As[kk][R0 + 4]);
            ulonglong2 bq0 = *reinterpret_cast<const ulonglong2*>(&Bs[kk][C0]);
            ulonglong2 bq1 = *reinterpret_cast<const ulonglong2*>(&Bs[kk][C0 + 4]);
            ull ap[8] = { pack2(a0.x), pack2(a0.y), pack2(a0.z), pack2(a0.w),
                          pack2(a1.x), pack2(a1.y), pack2(a1.z), pack2(a1.w) };
            ull bb[4] = { bq0.x, bq0.y, bq1.x, bq1.y };
#pragma unroll
            for (int r = 0; r < 8; r++) {
                fma2(acc[r][0], ap[r], bb[0]);
                fma2(acc[r][1], ap[r], bb[1]);
                fma2(acc[r][2], ap[r], bb[2]);
                fma2(acc[r][3], ap[r], bb[3]);
            }
        }
    }
    float bv[8], gv[8], bev[8];
#pragma unroll
    for (int q = 0; q < 8; q++) {
        bv[q] = __ldg(b_ua + C0 + q);
        gv[q] = __ldg(g_ua + C0 + q);
        bev[q] = __ldg(be_ua + C0 + q);
    }
#pragma unroll
    for (int rr = 0; rr < 8; ++rr) {
        float x[8];
#pragma unroll
        for (int c = 0; c < 4; c++) {
            float2 f = unpack2(acc[rr][c]);
            x[2 * c]     = gelu_exact(f.x + bv[2 * c]);
            x[2 * c + 1] = gelu_exact(f.y + bv[2 * c + 1]);
        }
        float sum = 0.0f;
#pragma unroll
        for (int q = 0; q < 8; q++) sum += x[q];
#pragma unroll
        for (int off = 1; off < 32; off <<= 1)
            sum += __shfl_xor_sync(0xffffffffu, sum, off);
        float mu = sum * (1.0f / HDIM);
        float sq = 0.0f;
#pragma unroll
        for (int q = 0; q < 8; q++) { float d = x[q] - mu; sq += d * d; }
#pragma unroll
        for (int off = 1; off < 32; off <<= 1)
            sq += __shfl_xor_sync(0xffffffffu, sq, off);
        float inv = rsqrtf(sq * (1.0f / HDIM) + 1e-5f);

        int cell = c0 + R0 + rr;
        int rg = regions[cell];
        float wn = expf(g_w[cell] - g_m[rg]) / g_denom[rg];
#pragma unroll
        for (int q = 0; q < 8; q++) {
            float y = ((x[q] - mu) * inv * gv[q] + bev[q]) * wn;
            atomicAdd(&g_agg[(size_t)rg * HDIM + C0 + q], y);
        }
    }
}

// ---------------- block reduce helper ----------------------------------------
__device__ __forceinline__ float block_sum256(float v, float* sbuf) {
#pragma unroll
    for (int off = 1; off < 32; off <<= 1)
        v += __shfl_xor_sync(0xffffffffu, v, off);
    int w = threadIdx.x >> 5;
    if ((threadIdx.x & 31) == 0) sbuf[w] = v;
    __syncthreads();
    float t = 0.0f;
#pragma unroll
    for (int i = 0; i < 8; i++) t += sbuf[i];
    __syncthreads();
    return t;
}

// ---------------- region: upd = LN(GELU(agg@w_up+b)), fused select + out -----
__global__ __launch_bounds__(256) void region_up_kernel(
    const float* __restrict__ w_up, const float* __restrict__ b_up,
    const float* __restrict__ g_up, const float* __restrict__ be_up,
    const float* __restrict__ z_fused, const float* __restrict__ raw_rw,
    float* __restrict__ out_fused)
{
    __shared__ float a_s[HDIM];
    __shared__ float sbuf[8];
    int r = blockIdx.x, tid = threadIdx.x;
    a_s[tid] = g_agg[(size_t)r * HDIM + tid];
    __syncthreads();
    float acc0 = b_up[tid], acc1 = b_up[tid + 256];
    for (int k = 0; k < HDIM; k++) {
        float a = a_s[k];
        acc0 = fmaf(a, w_up[(size_t)k * DDIM + tid], acc0);
        acc1 = fmaf(a, w_up[(size_t)k * DDIM + tid + 256], acc1);
    }
    float x0 = gelu_exact(acc0), x1 = gelu_exact(acc1);
    float mu = block_sum256(x0 + x1, sbuf) * (1.0f / DDIM);
    float d0 = x0 - mu, d1 = x1 - mu;
    float var = block_sum256(d0 * d0 + d1 * d1, sbuf) * (1.0f / DDIM);
    float inv = rsqrtf(var + 1e-5f);
    float u0 = d0 * inv * g_up[tid] + be_up[tid];
    float u1 = d1 * inv * g_up[tid + 256] + be_up[tid + 256];
    bool present = g_cnt[r] > 0.0f;
    float zf0 = z_fused[(size_t)r * DDIM + tid];
    float zf1 = z_fused[(size_t)r * DDIM + tid + 256];
    float s0 = present ? u0 : zf0;
    float s1 = present ? u1 : zf1;
    g_upd[(size_t)r * DDIM + tid] = s0;
    g_upd[(size_t)r * DDIM + tid + 256] = s1;
    float rw = 1.0f / (1.0f + expf(-__ldg(raw_rw)));
    out_fused[(size_t)r * DDIM + tid]       = rw * s0 + (1.0f - rw) * zf0;
    out_fused[(size_t)r * DDIM + tid + 256] = rw * s1 + (1.0f - rw) * zf1;
}

// ---------------- region: hb = LN(GELU(upd@w_d1+b)) --------------------------
__global__ __launch_bounds__(256) void region_hb_kernel(
    const float* __restrict__ w_d1, const float* __restrict__ b_d1,
    const float* __restrict__ g_d1, const float* __restrict__ be_d1)
{
    __shared__ float z_s[DDIM];
    __shared__ float sbuf[8];
    int r = blockIdx.x, tid = threadIdx.x;
    z_s[tid] = g_upd[(size_t)r * DDIM + tid];
    z_s[tid + 256] = g_upd[(size_t)r * DDIM + tid + 256];
    __syncthreads();
    float acc = b_d1[tid];
    for (int k = 0; k < DDIM; k++)
        acc = fmaf(z_s[k], w_d1[(size_t)k * HDIM + tid], acc);
    float x = gelu_exact(acc);
    float mu = block_sum256(x, sbuf) * (1.0f / HDIM);
    float d = x - mu;
    float var = block_sum256(d * d, sbuf) * (1.0f / HDIM);
    float inv = rsqrtf(var + 1e-5f);
    g_hb[(size_t)r * HDIM + tid] = d * inv * g_d1[tid] + be_d1[tid];
}

// ---------------- region: bcast = hb@w_d2 + b_d2 -----------------------------
__global__ __launch_bounds__(256) void region_bcast_kernel(
    const float* __restrict__ w_d2, const float* __restrict__ b_d2)
{
    __shared__ float h_s[HDIM];
    int r = blockIdx.x, tid = threadIdx.x;
    h_s[tid] = g_hb[(size_t)r * HDIM + tid];
    __syncthreads();
    float acc0 = b_d2[tid], acc1 = b_d2[tid + 256];
    for (int k = 0; k < HDIM; k++) {
        float h = h_s[k];
        acc0 = fmaf(h, w_d2[(size_t)k * DDIM + tid], acc0);
        acc1 = fmaf(h, w_d2[(size_t)k * DDIM + tid + 256], acc1);
    }
    g_bcast[(size_t)r * DDIM + tid] = acc0;
    g_bcast[(size_t)r * DDIM + tid + 256] = acc1;
}

// ---------------- launch -----------------------------------------------------
extern "C" void kernel_launch(void* const* d_in, const int* in_sizes, int n_in,
                              void* d_out, int out_size) {
    const float* z_local = (const float*)d_in[0];
    const float* z_fused = (const float*)d_in[1];
    const int*   regions = (const int*)d_in[2];
    const float* protos  = (const float*)d_in[3];
    const float* temp    = (const float*)d_in[4];
    const float* raw_rw  = (const float*)d_in[5];
    const float* w_ua = (const float*)d_in[6];
    const float* b_ua = (const float*)d_in[7];
    const float* g_ua = (const float*)d_in[8];
    const float* be_ua = (const float*)d_in[9];
    const float* w_up = (const float*)d_in[10];
    const float* b_up = (const float*)d_in[11];
    const float* g_up = (const float*)d_in[12];
    const float* be_up = (const float*)d_in[13];
    const float* w_d1 = (const float*)d_in[14];
    const float* b_d1 = (const float*)d_in[15];
    const float* g_d1 = (const float*)d_in[16];
    const float* be_d1 = (const float*)d_in[17];
    const float* w_d2 = (const float*)d_in[18];
    const float* b_d2 = (const float*)d_in[19];

    float* out_local = (float*)d_out;
    float* out_fused = out_local + (size_t)NCELLS * DDIM;

    init_kernel<<<(RREG * HDIM + 255) / 256, 256>>>();
    pass_kernel<0><<<NCELLS / TM, 256>>>(z_local, protos, regions, temp, raw_rw, nullptr);
    seg_max_kernel<<<NCELLS / 256, 256>>>(regions);
    seg_sum_kernel<<<NCELLS / 256, 256>>>(regions);
    h_agg_kernel<<<NCELLS / HM, 256>>>(z_local, w_ua, b_ua, g_ua, be_ua, regions);
    region_up_kernel<<<RREG, 256>>>(w_up, b_up, g_up, be_up, z_fused, raw_rw, out_fused);
    region_hb_kernel<<<RREG, 256>>>(w_d1, b_d1, g_d1, be_d1);
    region_bcast_kernel<<<RREG, 256>>>(w_d2, b_d2);
    pass_kernel<1><<<NCELLS / TM, 256>>>(z_local, nullptr, regions, temp, raw_rw, out_local);
}

// round 3
// speedup vs baseline: 1.0328x; 1.0328x over previous
#include <cuda_runtime.h>
#include <math.h>
#include <stdint.h>

#define NCELLS 131072
#define RREG   512
#define DDIM   512
#define HDIM   256

typedef unsigned long long ull;

// ---------------- scratch (device globals; no allocations allowed) ----------
__device__ float g_w[NCELLS];               // own-region softmax prob (pass 1)
__device__ float g_m[RREG];                 // segment max of w
__device__ float g_denom[RREG];             // segment sum of exp(w-m)
__device__ float g_cnt[RREG];               // segment counts
__device__ float g_agg[RREG * HDIM];        // weighted segment sum of h
__device__ float g_upd[RREG * DDIM];        // updated_z_fused
__device__ float g_hb[RREG * HDIM];         // LN(GELU(upd @ w_d1))
__device__ float g_bcast[RREG * DDIM];      // down_broadcast

__device__ __forceinline__ float gelu_exact(float x) {
    return 0.5f * x * (1.0f + erff(x * 0.70710678118654752440f));
}
__device__ __forceinline__ ull pack2(float a) {
    ull r; asm("mov.b64 %0, {%1,%1};" : "=l"(r) : "f"(a)); return r;
}
__device__ __forceinline__ float2 unpack2(ull v) {
    float2 r; asm("mov.b64 {%0,%1}, %2;" : "=f"(r.x), "=f"(r.y) : "l"(v)); return r;
}
__device__ __forceinline__ void fma2(ull &d, ull a, ull b) {
    asm("fma.rn.f32x2 %0, %1, %2, %3;" : "=l"(d) : "l"(a), "l"(b), "l"(d));
}

// ---------------- init: zero per-call scratch --------------------------------
__global__ void init_kernel() {
    int i = blockIdx.x * blockDim.x + threadIdx.x;
    if (i < RREG * HDIM) g_agg[i] = 0.0f;
    if (i < RREG) { g_m[i] = 0.0f; g_denom[i] = 0.0f; g_cnt[i] = 0.0f; }
}

// ---------------- big pass GEMM + fused online softmax -----------------------
// scores[i,j] = dot(z_local[i], B[j]) / temp ; consume via online softmax.
// MODE 0: B = protos, writes g_w[i] + fused atomicMax into g_m.
// MODE 1: B = g_upd,  writes out[i,:] = rw*bcast[reg[i],:]*w_i + (1-rw)*z[i,:]
#define TM 128
#define TN 128
#define TK 16
#define TMP 132
#define TNP 132

template <int MODE>
__global__ __launch_bounds__(256) void pass_kernel(
    const float* __restrict__ A, const float* __restrict__ Bext,
    const int* __restrict__ regions, const float* __restrict__ temp,
    const float* __restrict__ raw_rw, float* __restrict__ out)
{
    __shared__ __align__(16) float As[2][TK][TMP];
    __shared__ __align__(16) float Bs[2][TK][TNP];
    __shared__ int   reg_s[TM];
    __shared__ float w_s[TM];

    const float* B = (MODE == 0) ? Bext : (const float*)g_upd;
    const int tid = threadIdx.x;
    const int tx = tid & 15;          // 16 col-groups of 8
    const int ty = tid >> 4;          // 16 row-groups of 8
    const int c0 = blockIdx.x * TM;
    const int R0 = ty * 8;
    const float inv_t = 1.0f / __ldg(temp);

    if (tid < TM) reg_s[tid] = regions[c0 + tid];

    // per-thread staging coords: each thread carries 2 float4 of A, 2 of B
    const int lrow = tid >> 2;            // 0..63
    const int lseg = (tid & 3) * 4;       // k offset 0/4/8/12

    float4 pa0, pa1, pb0, pb1;
    const int NT = (RREG / TN) * (DDIM / TK);   // 4 * 32 = 128 tiles

    auto LD = [&](int u) {
        const int k0  = (u & 31) * TK;
        const int col0 = (u >> 5) * TN;
        const float* Ap = A + (size_t)(c0 + lrow) * DDIM + k0 + lseg;
        pa0 = *reinterpret_cast<const float4*>(Ap);
        pa1 = *reinterpret_cast<const float4*>(Ap + (size_t)64 * DDIM);
        const float* Bp = B + (size_t)(col0 + lrow) * DDIM + k0 + lseg;
        pb0 = *reinterpret_cast<const float4*>(Bp);
        pb1 = *reinterpret_cast<const float4*>(Bp + (size_t)64 * DDIM);
    };
    auto ST = [&](int b) {
        As[b][lseg + 0][lrow] = pa0.x; As[b][lseg + 1][lrow] = pa0.y;
        As[b][lseg + 2][lrow] = pa0.z; As[b][lseg + 3][lrow] = pa0.w;
        As[b][lseg + 0][lrow + 64] = pa1.x; As[b][lseg + 1][lrow + 64] = pa1.y;
        As[b][lseg + 2][lrow + 64] = pa1.z; As[b][lseg + 3][lrow + 64] = pa1.w;
        Bs[b][lseg + 0][lrow] = pb0.x; Bs[b][lseg + 1][lrow] = pb0.y;
        Bs[b][lseg + 2][lrow] = pb0.z; Bs[b][lseg + 3][lrow] = pb0.w;
        Bs[b][lseg + 0][lrow + 64] = pb1.x; Bs[b][lseg + 1][lrow + 64] = pb1.y;
        Bs[b][lseg + 2][lrow + 64] = pb1.z; Bs[b][lseg + 3][lrow + 64] = pb1.w;
    };

    float m_run[8], l_run[8], s_own[8];
#pragma unroll
    for (int r = 0; r < 8; r++) { m_run[r] = -3.4e38f; l_run[r] = 0.0f; s_own[r] = 0.0f; }

    ull acc[8][4];
#pragma unroll
    for (int r = 0; r < 8; r++)
#pragma unroll
        for (int c = 0; c < 4; c++) acc[r][c] = 0ull;

    LD(0); ST(0); LD(1);
    __syncthreads();

    for (int u = 0; u < NT; ++u) {
        const int b = u & 1;
        if (u + 1 < NT) ST(b ^ 1);        // store tile u+1 (regs loaded last iter)
        if (u + 2 < NT) LD(u + 2);        // prefetch; latency hidden by compute
#pragma unroll
        for (int kk = 0; kk < TK; ++kk) {
            float4 a0 = *reinterpret_cast<const float4*>(&As[b][kk][R0]);
            float4 a1 = *reinterpret_cast<const float4*>(&As[b][kk][R0 + 4]);
            ulonglong2 bq0 = *reinterpret_cast<const ulonglong2*>(&Bs[b][kk][tx * 8]);
            ulonglong2 bq1 = *reinterpret_cast<const ulonglong2*>(&Bs[b][kk][tx * 8 + 4]);
            ull ap[8] = { pack2(a0.x), pack2(a0.y), pack2(a0.z), pack2(a0.w),
                          pack2(a1.x), pack2(a1.y), pack2(a1.z), pack2(a1.w) };
            ull bb[4] = { bq0.x, bq0.y, bq1.x, bq1.y };
#pragma unroll
            for (int r = 0; r < 8; r++) {
                fma2(acc[r][0], ap[r], bb[0]);
                fma2(acc[r][1], ap[r], bb[1]);
                fma2(acc[r][2], ap[r], bb[2]);
                fma2(acc[r][3], ap[r], bb[3]);
            }
        }
        if ((u & 31) == 31) {
            // -------- online softmax update over this 128-col tile --------
            const int col0 = (u >> 5) * TN;
#pragma unroll
            for (int rr = 0; rr < 8; ++rr) {
                float s[8];
#pragma unroll
                for (int c = 0; c < 4; c++) {
                    float2 f = unpack2(acc[rr][c]);
                    s[2 * c] = f.x * inv_t; s[2 * c + 1] = f.y * inv_t;
                }
                float tmax = s[0];
#pragma unroll
                for (int q = 1; q < 8; q++) tmax = fmaxf(tmax, s[q]);
#pragma unroll
                for (int off = 1; off < 16; off <<= 1)
                    tmax = fmaxf(tmax, __shfl_xor_sync(0xffffffffu, tmax, off));
                float mo = m_run[rr];
                float mn = fmaxf(mo, tmax);
                float p = 0.0f;
#pragma unroll
                for (int q = 0; q < 8; q++) p += expf(s[q] - mn);
#pragma unroll
                for (int off = 1; off < 16; off <<= 1)
                    p += __shfl_xor_sync(0xffffffffu, p, off);
                l_run[rr] = l_run[rr] * expf(mo - mn) + p;
                m_run[rr] = mn;
                int d = reg_s[R0 + rr] - col0;
                if ((unsigned)d < (unsigned)TN && (d >> 3) == tx) s_own[rr] += s[d & 7];
#pragma unroll
                for (int c = 0; c < 4; c++) acc[rr][c] = 0ull;
            }
        }
        __syncthreads();
    }

    // -------- finalize per-row own-region prob --------
#pragma unroll
    for (int rr = 0; rr < 8; ++rr) {
        float so = s_own[rr];
#pragma unroll
        for (int off = 1; off < 16; off <<= 1)
            so += __shfl_xor_sync(0xffffffffu, so, off);
        float wv = expf(so - m_run[rr]) / l_run[rr];
        if (tx == 0) {
            if (MODE == 0) {
                g_w[c0 + R0 + rr] = wv;
                atomicMax((int*)&g_m[reg_s[R0 + rr]], __float_as_int(wv));  // wv > 0
            } else {
                w_s[R0 + rr] = wv;
            }
        }
    }
    if (MODE == 1) {
        __syncthreads();
        float xr = __ldg(raw_rw);
        float rw = 1.0f / (1.0f + expf(-xr));
        float orw = 1.0f - rw;
        for (int idx = tid; idx < TM * (DDIM / 4); idx += 256) {
            int row = idx >> 7;        // DDIM/4 = 128
            int c4 = idx & 127;
            int rg = reg_s[row];
            float wt = w_s[row];
            float4 bc = *reinterpret_cast<const float4*>(g_bcast + (size_t)rg * DDIM + c4 * 4);
            float4 zl = *reinterpret_cast<const float4*>(A + (size_t)(c0 + row) * DDIM + c4 * 4);
            float4 o;
            o.x = rw * (bc.x * wt) + orw * zl.x;
            o.y = rw * (bc.y * wt) + orw * zl.y;
            o.z = rw * (bc.z * wt) + orw * zl.z;
            o.w = rw * (bc.w * wt) + orw * zl.w;
            *reinterpret_cast<float4*>(out + (size_t)(c0 + row) * DDIM + c4 * 4) = o;
        }
    }
}

// ---------------- segment sum over exp(w - m) + counts -----------------------
__global__ void seg_sum_kernel(const int* __restrict__ regions) {
    int i = blockIdx.x * blockDim.x + threadIdx.x;
    if (i < NCELLS) {
        int r = regions[i];
        float e = expf(g_w[i] - g_m[r]);
        atomicAdd(&g_denom[r], e);
        atomicAdd(&g_cnt[r], 1.0f);
    }
}

// ---------------- h = LN(GELU(z @ w_ua + b_ua)); agg += h * w_norm -----------
#define HM 64
__global__ __launch_bounds__(256) void h_agg_kernel(
    const float* __restrict__ A, const float* __restrict__ w_ua,
    const float* __restrict__ b_ua, const float* __restrict__ g_ua,
    const float* __restrict__ be_ua, const int* __restrict__ regions)
{
    __shared__ __align__(16) float As[2][TK][68];     // 64+4
    __shared__ __align__(16) float Bs[2][TK][260];    // 256+4

    const int tid = threadIdx.x;
    const int tx = tid & 31;          // 32 col-groups of 8 (covers H=256)
    const int ty = tid >> 5;          // 8 row-groups of 8 (covers 64 rows)
    const int c0 = blockIdx.x * HM;
    const int R0 = ty * 8;
    const int C0 = tx * 8;

    // staging coords: A 1 float4/thread; B 4 float4/thread
    const int arow = tid >> 2;            // 0..63
    const int aseg = (tid & 3) * 4;
    const int bk   = tid >> 6;            // 0..3 (k within group of 4)
    const int bc4  = (tid & 63) * 4;      // col

    float4 pa, pb[4];
    const int NT = DDIM / TK;             // 32

    auto LD = [&](int u) {
        const int k0 = u * TK;
        pa = *reinterpret_cast<const float4*>(A + (size_t)(c0 + arow) * DDIM + k0 + aseg);
#pragma unroll
        for (int p = 0; p < 4; ++p)
            pb[p] = *reinterpret_cast<const float4*>(w_ua + (size_t)(k0 + bk + p * 4) * HDIM + bc4);
    };
    auto ST = [&](int b) {
        As[b][aseg + 0][arow] = pa.x; As[b][aseg + 1][arow] = pa.y;
        As[b][aseg + 2][arow] = pa.z; As[b][aseg + 3][arow] = pa.w;
#pragma unroll
        for (int p = 0; p < 4; ++p)
            *reinterpret_cast<float4*>(&Bs[b][bk + p * 4][bc4]) = pb[p];
    };

    ull acc[8][4];
#pragma unroll
    for (int r = 0; r < 8; r++)
#pragma unroll
        for (int c = 0; c < 4; c++) acc[r][c] = 0ull;

    LD(0); ST(0); LD(1);
    __syncthreads();

    for (int u = 0; u < NT; ++u) {
        const int b = u & 1;
        if (u + 1 < NT) ST(b ^ 1);
        if (u + 2 < NT) LD(u + 2);
#pragma unroll
        for (int kk = 0; kk < TK; ++kk) {
            float4 a0 = *reinterpret_cast<const float4*>(&As[b][kk][R0]);
            float4 a1 = *reinterpret_cast<const float4*>(&As[b][kk][R0 + 4]);
            ulonglong2 bq0 = *reinterpret_cast<const ulonglong2*>(&Bs[b][kk][C0]);
            ulonglong2 bq1 = *reinterpret_cast<const ulonglong2*>(&Bs[b][kk][C0 + 4]);
            ull ap[8] = { pack2(a0.x), pack2(a0.y), pack2(a0.z), pack2(a0.w),
                          pack2(a1.x), pack2(a1.y), pack2(a1.z), pack2(a1.w) };
            ull bb[4] = { bq0.x, bq0.y, bq1.x, bq1.y };
#pragma unroll
            for (int r = 0; r < 8; r++) {
                fma2(acc[r][0], ap[r], bb[0]);
                fma2(acc[r][1], ap[r], bb[1]);
                fma2(acc[r][2], ap[r], bb[2]);
                fma2(acc[r][3], ap[r], bb[3]);
            }
        }
        __syncthreads();
    }

    float bv[8], gv[8], bev[8];
#pragma unroll
    for (int q = 0; q < 8; q++) {
        bv[q] = __ldg(b_ua + C0 + q);
        gv[q] = __ldg(g_ua + C0 + q);
        bev[q] = __ldg(be_ua + C0 + q);
    }
#pragma unroll
    for (int rr = 0; rr < 8; ++rr) {
        float x[8];
#pragma unroll
        for (int c = 0; c < 4; c++) {
            float2 f = unpack2(acc[rr][c]);
            x[2 * c]     = gelu_exact(f.x + bv[2 * c]);
            x[2 * c + 1] = gelu_exact(f.y + bv[2 * c + 1]);
        }
        float sum = 0.0f;
#pragma unroll
        for (int q = 0; q < 8; q++) sum += x[q];
#pragma unroll
        for (int off = 1; off < 32; off <<= 1)
            sum += __shfl_xor_sync(0xffffffffu, sum, off);
        float mu = sum * (1.0f / HDIM);
        float sq = 0.0f;
#pragma unroll
        for (int q = 0; q < 8; q++) { float d = x[q] - mu; sq += d * d; }
#pragma unroll
        for (int off = 1; off < 32; off <<= 1)
            sq += __shfl_xor_sync(0xffffffffu, sq, off);
        float inv = rsqrtf(sq * (1.0f / HDIM) + 1e-5f);

        int cell = c0 + R0 + rr;
        int rg = regions[cell];
        float wn = expf(g_w[cell] - g_m[rg]) / g_denom[rg];
#pragma unroll
        for (int q = 0; q < 8; q++) {
            float y = ((x[q] - mu) * inv * gv[q] + bev[q]) * wn;
            atomicAdd(&g_agg[(size_t)rg * HDIM + C0 + q], y);
        }
    }
}

// ---------------- block reduce helper ----------------------------------------
__device__ __forceinline__ float block_sum256(float v, float* sbuf) {
#pragma unroll
    for (int off = 1; off < 32; off <<= 1)
        v += __shfl_xor_sync(0xffffffffu, v, off);
    int w = threadIdx.x >> 5;
    if ((threadIdx.x & 31) == 0) sbuf[w] = v;
    __syncthreads();
    float t = 0.0f;
#pragma unroll
    for (int i = 0; i < 8; i++) t += sbuf[i];
    __syncthreads();
    return t;
}

// ---------------- region: upd = LN(GELU(agg@w_up+b)), fused select + out -----
__global__ __launch_bounds__(256) void region_up_kernel(
    const float* __restrict__ w_up, const float* __restrict__ b_up,
    const float* __restrict__ g_up, const float* __restrict__ be_up,
    const float* __restrict__ z_fused, const float* __restrict__ raw_rw,
    float* __restrict__ out_fused)
{
    __shared__ float a_s[HDIM];
    __shared__ float sbuf[8];
    int r = blockIdx.x, tid = threadIdx.x;
    a_s[tid] = g_agg[(size_t)r * HDIM + tid];
    __syncthreads();
    float acc0 = b_up[tid], acc1 = b_up[tid + 256];
    for (int k = 0; k < HDIM; k++) {
        float a = a_s[k];
        acc0 = fmaf(a, w_up[(size_t)k * DDIM + tid], acc0);
        acc1 = fmaf(a, w_up[(size_t)k * DDIM + tid + 256], acc1);
    }
    float x0 = gelu_exact(acc0), x1 = gelu_exact(acc1);
    float mu = block_sum256(x0 + x1, sbuf) * (1.0f / DDIM);
    float d0 = x0 - mu, d1 = x1 - mu;
    float var = block_sum256(d0 * d0 + d1 * d1, sbuf) * (1.0f / DDIM);
    float inv = rsqrtf(var + 1e-5f);
    float u0 = d0 * inv * g_up[tid] + be_up[tid];
    float u1 = d1 * inv * g_up[tid + 256] + be_up[tid + 256];
    bool present = g_cnt[r] > 0.0f;
    float zf0 = z_fused[(size_t)r * DDIM + tid];
    float zf1 = z_fused[(size_t)r * DDIM + tid + 256];
    float s0 = present ? u0 : zf0;
    float s1 = present ? u1 : zf1;
    g_upd[(size_t)r * DDIM + tid] = s0;
    g_upd[(size_t)r * DDIM + tid + 256] = s1;
    float rw = 1.0f / (1.0f + expf(-__ldg(raw_rw)));
    out_fused[(size_t)r * DDIM + tid]       = rw * s0 + (1.0f - rw) * zf0;
    out_fused[(size_t)r * DDIM + tid + 256] = rw * s1 + (1.0f - rw) * zf1;
}

// ---------------- region: hb = LN(GELU(upd@w_d1+b)) --------------------------
__global__ __launch_bounds__(256) void region_hb_kernel(
    const float* __restrict__ w_d1, const float* __restrict__ b_d1,
    const float* __restrict__ g_d1, const float* __restrict__ be_d1)
{
    __shared__ float z_s[DDIM];
    __shared__ float sbuf[8];
    int r = blockIdx.x, tid = threadIdx.x;
    z_s[tid] = g_upd[(size_t)r * DDIM + tid];
    z_s[tid + 256] = g_upd[(size_t)r * DDIM + tid + 256];
    __syncthreads();
    float acc = b_d1[tid];
    for (int k = 0; k < DDIM; k++)
        acc = fmaf(z_s[k], w_d1[(size_t)k * HDIM + tid], acc);
    float x = gelu_exact(acc);
    float mu = block_sum256(x, sbuf) * (1.0f / HDIM);
    float d = x - mu;
    float var = block_sum256(d * d, sbuf) * (1.0f / HDIM);
    float inv = rsqrtf(var + 1e-5f);
    g_hb[(size_t)r * HDIM + tid] = d * inv * g_d1[tid] + be_d1[tid];
}

// ---------------- region: bcast = hb@w_d2 + b_d2 -----------------------------
__global__ __launch_bounds__(256) void region_bcast_kernel(
    const float* __restrict__ w_d2, const float* __restrict__ b_d2)
{
    __shared__ float h_s[HDIM];
    int r = blockIdx.x, tid = threadIdx.x;
    h_s[tid] = g_hb[(size_t)r * HDIM + tid];
    __syncthreads();
    float acc0 = b_d2[tid], acc1 = b_d2[tid + 256];
    for (int k = 0; k < HDIM; k++) {
        float h = h_s[k];
        acc0 = fmaf(h, w_d2[(size_t)k * DDIM + tid], acc0);
        acc1 = fmaf(h, w_d2[(size_t)k * DDIM + tid + 256], acc1);
    }
    g_bcast[(size_t)r * DDIM + tid] = acc0;
    g_bcast[(size_t)r * DDIM + tid + 256] = acc1;
}

// ---------------- launch -----------------------------------------------------
extern "C" void kernel_launch(void* const* d_in, const int* in_sizes, int n_in,
                              void* d_out, int out_size) {
    const float* z_local = (const float*)d_in[0];
    const float* z_fused = (const float*)d_in[1];
    const int*   regions = (const int*)d_in[2];
    const float* protos  = (const float*)d_in[3];
    const float* temp    = (const float*)d_in[4];
    const float* raw_rw  = (const float*)d_in[5];
    const float* w_ua = (const float*)d_in[6];
    const float* b_ua = (const float*)d_in[7];
    const float* g_ua = (const float*)d_in[8];
    const float* be_ua = (const float*)d_in[9];
    const float* w_up = (const float*)d_in[10];
    const float* b_up = (const float*)d_in[11];
    const float* g_up = (const float*)d_in[12];
    const float* be_up = (const float*)d_in[13];
    const float* w_d1 = (const float*)d_in[14];
    const float* b_d1 = (const float*)d_in[15];
    const float* g_d1 = (const float*)d_in[16];
    const float* be_d1 = (const float*)d_in[17];
    const float* w_d2 = (const float*)d_in[18];
    const float* b_d2 = (const float*)d_in[19];

    float* out_local = (float*)d_out;
    float* out_fused = out_local + (size_t)NCELLS * DDIM;

    init_kernel<<<(RREG * HDIM + 255) / 256, 256>>>();
    pass_kernel<0><<<NCELLS / TM, 256>>>(z_local, protos, regions, temp, raw_rw, nullptr);
    seg_sum_kernel<<<NCELLS / 256, 256>>>(regions);
    h_agg_kernel<<<NCELLS / HM, 256>>>(z_local, w_ua, b_ua, g_ua, be_ua, regions);
    region_up_kernel<<<RREG, 256>>>(w_up, b_up, g_up, be_up, z_fused, raw_rw, out_fused);
    region_hb_kernel<<<RREG, 256>>>(w_d1, b_d1, g_d1, be_d1);
    region_bcast_kernel<<<RREG, 256>>>(w_d2, b_d2);
    pass_kernel<1><<<NCELLS / TM, 256>>>(z_local, nullptr, regions, temp, raw_rw, out_local);
}

// round 6
// speedup vs baseline: 1.9464x; 1.8846x over previous
#include <cuda_runtime.h>
#include <math.h>
#include <stdint.h>

#define NCELLS 131072
#define RREG   512
#define DDIM   512
#define HDIM   256

typedef unsigned long long ull;
typedef unsigned int u32;

#if defined(__CUDA_ARCH_FEAT_SM103_ALL) || defined(__CUDA_ARCH_FEAT_SM100_ALL) || defined(__CUDA_ARCH_FEAT_SM101_ALL)
#define HAS_TCGEN05 1
#else
#define HAS_TCGEN05 0
#endif

__device__ float g_w[NCELLS];
__device__ float g_m[RREG];
__device__ float g_denom[RREG];
__device__ float g_cnt[RREG];
__device__ float g_agg[RREG * HDIM];
__device__ float g_upd[RREG * DDIM];
__device__ float g_hb[RREG * HDIM];
__device__ float g_bcast[RREG * DDIM];

__device__ __forceinline__ float gelu_exact(float x) {
    return 0.5f * x * (1.0f + erff(x * 0.70710678118654752440f));
}
__device__ __forceinline__ ull pack2(float a) {
    ull r; asm("mov.b64 %0, {%1,%1};" : "=l"(r) : "f"(a)); return r;
}
__device__ __forceinline__ float2 unpack2(ull v) {
    float2 r; asm("mov.b64 {%0,%1}, %2;" : "=f"(r.x), "=f"(r.y) : "l"(v)); return r;
}
__device__ __forceinline__ void fma2(ull &d, ull a, ull b) {
    asm("fma.rn.f32x2 %0, %1, %2, %3;" : "=l"(d) : "l"(a), "l"(b), "l"(d));
}

#if HAS_TCGEN05
// ---------------- tcgen05 helpers (compiled only on 'a' targets) -------------
__device__ __forceinline__ u32 smem_u32(const void* p) {
    u32 a; asm("{ .reg .u64 t; cvta.to.shared.u64 t, %1; cvt.u32.u64 %0, t; }" : "=r"(a) : "l"(p));
    return a;
}
__device__ __forceinline__ bool elect_one() {
    u32 pred;
    asm volatile("{\n\t.reg .pred p;\n\telect.sync _|p, 0xFFFFFFFF;\n\tselp.b32 %0, 1, 0, p;\n\t}" : "=r"(pred));
    return pred != 0;
}
__device__ __forceinline__ float tf32f(float x) {
    u32 u; asm("cvt.rna.tf32.f32 %0, %1;" : "=r"(u) : "f"(x)); return __uint_as_float(u);
}
__device__ __forceinline__ void mbar_init(u32 addr, u32 cnt) {
    asm volatile("mbarrier.init.shared.b64 [%0], %1;" :: "r"(addr), "r"(cnt) : "memory");
}
__device__ __forceinline__ void mbar_inval(u32 addr) {
    asm volatile("mbarrier.inval.shared.b64 [%0];" :: "r"(addr) : "memory");
}
__device__ __forceinline__ void mbar_wait(u32 addr, u32 parity) {
    asm volatile(
        "{\n\t.reg .pred P;\n\t"
        "WL_%=:\n\t"
        "mbarrier.try_wait.parity.acquire.cta.shared::cta.b64 P, [%0], %1, 0x989680;\n\t"
        "@P bra.uni WD_%=;\n\t"
        "bra.uni WL_%=;\n\t"
        "WD_%=:\n\t}"
        :: "r"(addr), "r"(parity) : "memory");
}
__device__ __forceinline__ void tc_alloc(u32 smem_dst, u32 ncols) {
    asm volatile("tcgen05.alloc.cta_group::1.sync.aligned.shared::cta.b32 [%0], %1;"
                 :: "r"(smem_dst), "r"(ncols) : "memory");
}
__device__ __forceinline__ void tc_relinquish() {
    asm volatile("tcgen05.relinquish_alloc_permit.cta_group::1.sync.aligned;");
}
__device__ __forceinline__ void tc_dealloc(u32 tmem, u32 ncols) {
    asm volatile("tcgen05.dealloc.cta_group::1.sync.aligned.b32 %0, %1;" :: "r"(tmem), "r"(ncols));
}
__device__ __forceinline__ void tc_commit(u32 mbar) {
    asm volatile("tcgen05.commit.cta_group::1.mbarrier::arrive::one.shared::cluster.b64 [%0];"
                 :: "r"(mbar) : "memory");
}
__device__ __forceinline__ void tc_fence_after() {
    asm volatile("tcgen05.fence::after_thread_sync;" ::: "memory");
}
__device__ __forceinline__ void fence_proxy() {
    asm volatile("fence.proxy.async.shared::cta;" ::: "memory");
}
__device__ __forceinline__ void mma_tf32_ss(u32 d, ull ad, ull bd, u32 idesc, bool acc) {
    u32 e = acc ? 1u : 0u;
    asm volatile(
        "{\n\t.reg .pred p;\n\tsetp.ne.u32 p, %5, 0;\n\t"
        "tcgen05.mma.cta_group::1.kind::tf32 [%0], %1, %2, %3, {%4, %4, %4, %4}, p;\n\t}"
        :: "r"(d), "l"(ad), "l"(bd), "r"(idesc), "r"(0u), "r"(e) : "memory");
}
__device__ __forceinline__ void tc_wait_ld() {
    asm volatile("tcgen05.wait::ld.sync.aligned;" ::: "memory");
}
__device__ __forceinline__ void ldtm32(u32* r, u32 tmem_addr) {
    asm volatile(
        "tcgen05.ld.sync.aligned.32x32b.x32.b32 "
        "{%0, %1, %2, %3, %4, %5, %6, %7, "
        " %8, %9, %10, %11, %12, %13, %14, %15, "
        " %16, %17, %18, %19, %20, %21, %22, %23, "
        " %24, %25, %26, %27, %28, %29, %30, %31}, [%32];"
        : "=r"(r[0]), "=r"(r[1]), "=r"(r[2]), "=r"(r[3]),
          "=r"(r[4]), "=r"(r[5]), "=r"(r[6]), "=r"(r[7]),
          "=r"(r[8]), "=r"(r[9]), "=r"(r[10]), "=r"(r[11]),
          "=r"(r[12]), "=r"(r[13]), "=r"(r[14]), "=r"(r[15]),
          "=r"(r[16]), "=r"(r[17]), "=r"(r[18]), "=r"(r[19]),
          "=r"(r[20]), "=r"(r[21]), "=r"(r[22]), "=r"(r[23]),
          "=r"(r[24]), "=r"(r[25]), "=r"(r[26]), "=r"(r[27]),
          "=r"(r[28]), "=r"(r[29]), "=r"(r[30]), "=r"(r[31])
        : "r"(tmem_addr));
}
__device__ __forceinline__ ull smem_desc(u32 base) {
    return ((ull)2 << 61) | ((ull)1 << 46) | ((ull)64 << 32) | ((ull)1 << 16)
         | ((ull)(base >> 4) & 0x3FFF);
}
#define SWZ(x) ((x) ^ ((((u32)(x)) >> 3) & 0x70))
#endif  // HAS_TCGEN05

__global__ void init_kernel() {
    int i = blockIdx.x * blockDim.x + threadIdx.x;
    if (i < RREG * HDIM) g_agg[i] = 0.0f;
    if (i < RREG) { g_m[i] = 0.0f; g_denom[i] = 0.0f; g_cnt[i] = 0.0f; }
}

// ---------------- pass kernel: scores + fused row softmax --------------------
// MODE 0: B = protos, writes g_w[i] + fused atomicMax into g_m.
// MODE 1: B = g_upd,  writes out[i,:] = rw*bcast[reg[i],:]*w_i + (1-rw)*z[i,:]
#define PT_M     128
#define PT_KC    32
#define PT_STEPS ((DDIM / PT_KC) * 4)
#define TILE_B   16384
#define SM_CTRL  2048
#define SM_TOTAL (SM_CTRL + 8 * TILE_B)
#define TOFF(i)  (SM_CTRL + (i) * TILE_B)
#define IDESC_TF32 ((1u << 4) | (2u << 7) | (2u << 10) | ((128u / 8) << 17) | ((128u / 16) << 24))

template <int MODE>
__global__ __launch_bounds__(256) void pass_tc(
    const float* __restrict__ A, const float* __restrict__ Bext,
    const int* __restrict__ regions, const float* __restrict__ temp,
    const float* __restrict__ raw_rw, float* __restrict__ out)
{
    extern __shared__ __align__(1024) char smem[];
    const float* B = (MODE == 0) ? Bext : (const float*)g_upd;
    const int tid = threadIdx.x;
    const int c0 = blockIdx.x * PT_M;
    const float inv_t = 1.0f / __ldg(temp);

    int*   reg_s = (int*)(smem + 32);     // 128 ints
    float* w_s   = (float*)(smem + 544);  // 128 floats

#if HAS_TCGEN05
    // ================= tcgen05 3xTF32 path =================
    const u32 sb = smem_u32(smem);
    const int wid = tid >> 5;
    const int lid = tid & 31;

    // alloc / relinquish are FULL-WARP collectives (test_dequant pattern).
    if (wid == 0) {
        tc_alloc(sb + 0, 512);
    } else {
        tc_relinquish();
    }
    if (tid == 0) { mbar_init(sb + 8, 1); mbar_init(sb + 16, 1); }
    if (tid < PT_M) reg_s[tid] = regions[c0 + tid];
    __syncthreads();
    u32 tmem;
    asm volatile("ld.shared.b32 %0, [%1];" : "=r"(tmem) : "r"(sb + 0));

    const int lrow = tid >> 1;
    const int lc0  = (tid & 1) * 4;

    int ph0 = 0, ph1 = 0;
    for (int t = 0; t < PT_STEPS; ++t) {
        if (t >= 2) {
            if (t & 1) { mbar_wait(sb + 16, ph1); ph1 ^= 1; }
            else       { mbar_wait(sb + 8,  ph0); ph0 ^= 1; }
        }
        const int s = t & 1, n = t & 3, k = t >> 2;
        {
            const float* src = B + (size_t)(n * 128 + lrow) * DDIM + k * PT_KC + lc0 * 4;
            char* bh = smem + TOFF(4 + 2 * s);
            char* bl = smem + TOFF(5 + 2 * s);
#pragma unroll
            for (int i = 0; i < 4; ++i) {
                float4 v = *(const float4*)(src + i * 4);
                float4 h, l;
                h.x = tf32f(v.x); l.x = tf32f(v.x - h.x);
                h.y = tf32f(v.y); l.y = tf32f(v.y - h.y);
                h.z = tf32f(v.z); l.z = tf32f(v.z - h.z);
                h.w = tf32f(v.w); l.w = tf32f(v.w - h.w);
                u32 off = SWZ(lrow * 128 + (lc0 + i) * 16);
                *(float4*)(bh + off) = h;
                *(float4*)(bl + off) = l;
            }
        }
        if (n == 0) {
            const float* src = A + (size_t)(c0 + lrow) * DDIM + k * PT_KC + lc0 * 4;
            char* ah = smem + TOFF(0 + 2 * (k & 1));
            char* al = smem + TOFF(1 + 2 * (k & 1));
#pragma unroll
            for (int i = 0; i < 4; ++i) {
                float4 v = *(const float4*)(src + i * 4);
                float4 h, l;
                h.x = tf32f(v.x); l.x = tf32f(v.x - h.x);
                h.y = tf32f(v.y); l.y = tf32f(v.y - h.y);
                h.z = tf32f(v.z); l.z = tf32f(v.z - h.z);
                h.w = tf32f(v.w); l.w = tf32f(v.w - h.w);
                u32 off = SWZ(lrow * 128 + (lc0 + i) * 16);
                *(float4*)(ah + off) = h;
                *(float4*)(al + off) = l;
            }
        }
        __syncthreads();
        if (wid == 0 && elect_one()) {
            fence_proxy();
            ull adh = smem_desc(sb + TOFF(0 + 2 * (k & 1)));
            ull adl = smem_desc(sb + TOFF(1 + 2 * (k & 1)));
            ull bdh = smem_desc(sb + TOFF(4 + 2 * s));
            ull bdl = smem_desc(sb + TOFF(5 + 2 * s));
            u32 d = tmem + n * 128;
#pragma unroll
            for (int ks = 0; ks < 4; ++ks) {
                mma_tf32_ss(d, adh + ks * 2, bdh + ks * 2, IDESC_TF32, !(k == 0 && ks == 0));
                mma_tf32_ss(d, adh + ks * 2, bdl + ks * 2, IDESC_TF32, true);
                mma_tf32_ss(d, adl + ks * 2, bdh + ks * 2, IDESC_TF32, true);
            }
            tc_commit(sb + 8 + s * 8);
        }
    }
    mbar_wait(sb + 8, ph0);
    mbar_wait(sb + 16, ph1);
    __syncthreads();
    tc_fence_after();

    if (wid < 4) {
        const int row = wid * 32 + lid;
        const int jown = reg_s[row];
        const int jch = jown >> 5, jidx = jown & 31;
        float m = -3.4e38f, l = 0.0f, sown = 0.0f;
#pragma unroll
        for (int ch = 0; ch < 16; ++ch) {
            u32 r[32];
            ldtm32(r, tmem + ch * 32);
            tc_wait_ld();
            float sv[32];
#pragma unroll
            for (int q = 0; q < 32; ++q) sv[q] = __uint_as_float(r[q]) * inv_t;
            float cmax = sv[0];
#pragma unroll
            for (int q = 1; q < 32; ++q) cmax = fmaxf(cmax, sv[q]);
            float mn = fmaxf(m, cmax);
            float p = 0.0f;
#pragma unroll
            for (int q = 0; q < 32; ++q) p += expf(sv[q] - mn);
            l = l * expf(m - mn) + p;
            m = mn;
            if (ch == jch) {
#pragma unroll
                for (int q = 0; q < 32; ++q) sown = (q == jidx) ? sv[q] : sown;
            }
        }
        float wv = expf(sown - m) / l;
        if (MODE == 0) {
            g_w[c0 + row] = wv;
            atomicMax((int*)&g_m[jown], __float_as_int(wv));   // wv > 0 always
        } else {
            w_s[row] = wv;
        }
    }
    __syncthreads();
    if (tid == 0) { mbar_inval(sb + 8); mbar_inval(sb + 16); }
    __syncthreads();
    if (wid == 0) tc_dealloc(tmem, 512);

#else
    // ================= f32x2 fallback path (base sm_103 PTX) =================
    float* As0 = (float*)(smem + SM_CTRL);
    float* Bs0 = As0 + 2 * 16 * 132;
    const int tx = tid & 15;
    const int ty = tid >> 4;
    const int R0 = ty * 8;
    if (tid < PT_M) reg_s[tid] = regions[c0 + tid];

    const int lrow = tid >> 2;
    const int lseg = (tid & 3) * 4;
    float4 pa0, pa1, pb0, pb1;
    const int NT = (RREG / 128) * (DDIM / 16);

    auto LD = [&](int u) {
        const int k0  = (u & 31) * 16;
        const int col0 = (u >> 5) * 128;
        const float* Ap = A + (size_t)(c0 + lrow) * DDIM + k0 + lseg;
        pa0 = *reinterpret_cast<const float4*>(Ap);
        pa1 = *reinterpret_cast<const float4*>(Ap + (size_t)64 * DDIM);
        const float* Bp = B + (size_t)(col0 + lrow) * DDIM + k0 + lseg;
        pb0 = *reinterpret_cast<const float4*>(Bp);
        pb1 = *reinterpret_cast<const float4*>(Bp + (size_t)64 * DDIM);
    };
    auto ST = [&](int b) {
        float* As = As0 + b * 16 * 132;
        float* Bs = Bs0 + b * 16 * 132;
        As[(lseg + 0) * 132 + lrow] = pa0.x; As[(lseg + 1) * 132 + lrow] = pa0.y;
        As[(lseg + 2) * 132 + lrow] = pa0.z; As[(lseg + 3) * 132 + lrow] = pa0.w;
        As[(lseg + 0) * 132 + lrow + 64] = pa1.x; As[(lseg + 1) * 132 + lrow + 64] = pa1.y;
        As[(lseg + 2) * 132 + lrow + 64] = pa1.z; As[(lseg + 3) * 132 + lrow + 64] = pa1.w;
        Bs[(lseg + 0) * 132 + lrow] = pb0.x; Bs[(lseg + 1) * 132 + lrow] = pb0.y;
        Bs[(lseg + 2) * 132 + lrow] = pb0.z; Bs[(lseg + 3) * 132 + lrow] = pb0.w;
        Bs[(lseg + 0) * 132 + lrow + 64] = pb1.x; Bs[(lseg + 1) * 132 + lrow + 64] = pb1.y;
        Bs[(lseg + 2) * 132 + lrow + 64] = pb1.z; Bs[(lseg + 3) * 132 + lrow + 64] = pb1.w;
    };

    float m_run[8], l_run[8], s_own[8];
#pragma unroll
    for (int r = 0; r < 8; r++) { m_run[r] = -3.4e38f; l_run[r] = 0.0f; s_own[r] = 0.0f; }

    ull acc[8][4];
#pragma unroll
    for (int r = 0; r < 8; r++)
#pragma unroll
        for (int c = 0; c < 4; c++) acc[r][c] = 0ull;

    LD(0); ST(0); LD(1);
    __syncthreads();

    for (int u = 0; u < NT; ++u) {
        const int b = u & 1;
        if (u + 1 < NT) ST(b ^ 1);
        if (u + 2 < NT) LD(u + 2);
        const float* As = As0 + b * 16 * 132;
        const float* Bs = Bs0 + b * 16 * 132;
#pragma unroll
        for (int kk = 0; kk < 16; ++kk) {
            float4 a0 = *reinterpret_cast<const float4*>(&As[kk * 132 + R0]);
            float4 a1 = *reinterpret_cast<const float4*>(&As[kk * 132 + R0 + 4]);
            ulonglong2 bq0 = *reinterpret_cast<const ulonglong2*>(&Bs[kk * 132 + tx * 8]);
            ulonglong2 bq1 = *reinterpret_cast<const ulonglong2*>(&Bs[kk * 132 + tx * 8 + 4]);
            ull ap[8] = { pack2(a0.x), pack2(a0.y), pack2(a0.z), pack2(a0.w),
                          pack2(a1.x), pack2(a1.y), pack2(a1.z), pack2(a1.w) };
            ull bb[4] = { bq0.x, bq0.y, bq1.x, bq1.y };
#pragma unroll
            for (int r = 0; r < 8; r++) {
                fma2(acc[r][0], ap[r], bb[0]);
                fma2(acc[r][1], ap[r], bb[1]);
                fma2(acc[r][2], ap[r], bb[2]);
                fma2(acc[r][3], ap[r], bb[3]);
            }
        }
        if ((u & 31) == 31) {
            const int col0 = (u >> 5) * 128;
#pragma unroll
            for (int rr = 0; rr < 8; ++rr) {
                float s[8];
#pragma unroll
                for (int c = 0; c < 4; c++) {
                    float2 f = unpack2(acc[rr][c]);
                    s[2 * c] = f.x * inv_t; s[2 * c + 1] = f.y * inv_t;
                }
                float tmax = s[0];
#pragma unroll
                for (int q = 1; q < 8; q++) tmax = fmaxf(tmax, s[q]);
#pragma unroll
                for (int off = 1; off < 16; off <<= 1)
                    tmax = fmaxf(tmax, __shfl_xor_sync(0xffffffffu, tmax, off));
                float mo = m_run[rr];
                float mn = fmaxf(mo, tmax);
                float p = 0.0f;
#pragma unroll
                for (int q = 0; q < 8; q++) p += expf(s[q] - mn);
#pragma unroll
                for (int off = 1; off < 16; off <<= 1)
                    p += __shfl_xor_sync(0xffffffffu, p, off);
                l_run[rr] = l_run[rr] * expf(mo - mn) + p;
                m_run[rr] = mn;
                int d = reg_s[R0 + rr] - col0;
                if ((unsigned)d < 128u && (d >> 3) == tx) s_own[rr] += s[d & 7];
#pragma unroll
                for (int c = 0; c < 4; c++) acc[rr][c] = 0ull;
            }
        }
        __syncthreads();
    }

#pragma unroll
    for (int rr = 0; rr < 8; ++rr) {
        float so = s_own[rr];
#pragma unroll
        for (int off = 1; off < 16; off <<= 1)
            so += __shfl_xor_sync(0xffffffffu, so, off);
        float wv = expf(so - m_run[rr]) / l_run[rr];
        if (tx == 0) {
            if (MODE == 0) {
                g_w[c0 + R0 + rr] = wv;
                atomicMax((int*)&g_m[reg_s[R0 + rr]], __float_as_int(wv));
            } else {
                w_s[R0 + rr] = wv;
            }
        }
    }
    __syncthreads();
#endif

    if (MODE == 1) {
        float xr = __ldg(raw_rw);
        float rw = 1.0f / (1.0f + expf(-xr));
        float orw = 1.0f - rw;
        for (int idx = tid; idx < PT_M * (DDIM / 4); idx += 256) {
            int row = idx >> 7;
            int c4 = idx & 127;
            int rg = reg_s[row];
            float wt = w_s[row];
            float4 bc = *reinterpret_cast<const float4*>(g_bcast + (size_t)rg * DDIM + c4 * 4);
            float4 zl = *reinterpret_cast<const float4*>(A + (size_t)(c0 + row) * DDIM + c4 * 4);
            float4 o;
            o.x = rw * (bc.x * wt) + orw * zl.x;
            o.y = rw * (bc.y * wt) + orw * zl.y;
            o.z = rw * (bc.z * wt) + orw * zl.z;
            o.w = rw * (bc.w * wt) + orw * zl.w;
            *reinterpret_cast<float4*>(out + (size_t)(c0 + row) * DDIM + c4 * 4) = o;
        }
    }
}

__global__ void seg_sum_kernel(const int* __restrict__ regions) {
    int i = blockIdx.x * blockDim.x + threadIdx.x;
    if (i < NCELLS) {
        int r = regions[i];
        float e = expf(g_w[i] - g_m[r]);
        atomicAdd(&g_denom[r], e);
        atomicAdd(&g_cnt[r], 1.0f);
    }
}

#define TK 16
#define HM 64
__global__ __launch_bounds__(256, 2) void h_agg_kernel(
    const float* __restrict__ A, const float* __restrict__ w_ua,
    const float* __restrict__ b_ua, const float* __restrict__ g_ua,
    const float* __restrict__ be_ua, const int* __restrict__ regions)
{
    __shared__ __align__(16) float As[2][TK][68];
    __shared__ __align__(16) float Bs[2][TK][260];

    const int tid = threadIdx.x;
    const int tx = tid & 31;
    const int ty = tid >> 5;
    const int c0 = blockIdx.x * HM;
    const int R0 = ty * 8;
    const int C0 = tx * 8;

    const int arow = tid >> 2;
    const int aseg = (tid & 3) * 4;
    const int bk   = tid >> 6;
    const int bc4  = (tid & 63) * 4;

    float4 pa, pb[4];
    const int NT = DDIM / TK;

    auto LD = [&](int u) {
        const int k0 = u * TK;
        pa = *reinterpret_cast<const float4*>(A + (size_t)(c0 + arow) * DDIM + k0 + aseg);
#pragma unroll
        for (int p = 0; p < 4; ++p)
            pb[p] = *reinterpret_cast<const float4*>(w_ua + (size_t)(k0 + bk + p * 4) * HDIM + bc4);
    };
    auto ST = [&](int b) {
        As[b][aseg + 0][arow] = pa.x; As[b][aseg + 1][arow] = pa.y;
        As[b][aseg + 2][arow] = pa.z; As[b][aseg + 3][arow] = pa.w;
#pragma unroll
        for (int p = 0; p < 4; ++p)
            *reinterpret_cast<float4*>(&Bs[b][bk + p * 4][bc4]) = pb[p];
    };

    ull acc[8][4];
#pragma unroll
    for (int r = 0; r < 8; r++)
#pragma unroll
        for (int c = 0; c < 4; c++) acc[r][c] = 0ull;

    LD(0); ST(0); LD(1);
    __syncthreads();

    for (int u = 0; u < NT; ++u) {
        const int b = u & 1;
        if (u + 1 < NT) ST(b ^ 1);
        if (u + 2 < NT) LD(u + 2);
#pragma unroll
        for (int kk = 0; kk < TK; ++kk) {
            float4 a0 = *reinterpret_cast<const float4*>(&As[b][kk][R0]);
            float4 a1 = *reinterpret_cast<const float4*>(&As[b][kk][R0 + 4]);
            ulonglong2 bq0 = *reinterpret_cast<const ulonglong2*>(&Bs[b][kk][C0]);
            ulonglong2 bq1 = *reinterpret_cast<const ulonglong2*>(&Bs[b][kk][C0 + 4]);
            ull ap[8] = { pack2(a0.x), pack2(a0.y), pack2(a0.z), pack2(a0.w),
                          pack2(a1.x), pack2(a1.y), pack2(a1.z), pack2(a1.w) };
            ull bb[4] = { bq0.x, bq0.y, bq1.x, bq1.y };
#pragma unroll
            for (int r = 0; r < 8; r++) {
                fma2(acc[r][0], ap[r], bb[0]);
                fma2(acc[r][1], ap[r], bb[1]);
                fma2(acc[r][2], ap[r], bb[2]);
                fma2(acc[r][3], ap[r], bb[3]);
            }
        }
        __syncthreads();
    }

    float bv[8], gv[8], bev[8];
#pragma unroll
    for (int q = 0; q < 8; q++) {
        bv[q] = __ldg(b_ua + C0 + q);
        gv[q] = __ldg(g_ua + C0 + q);
        bev[q] = __ldg(be_ua + C0 + q);
    }
#pragma unroll
    for (int rr = 0; rr < 8; ++rr) {
        float x[8];
#pragma unroll
        for (int c = 0; c < 4; c++) {
            float2 f = unpack2(acc[rr][c]);
            x[2 * c]     = gelu_exact(f.x + bv[2 * c]);
            x[2 * c + 1] = gelu_exact(f.y + bv[2 * c + 1]);
        }
        float sum = 0.0f;
#pragma unroll
        for (int q = 0; q < 8; q++) sum += x[q];
#pragma unroll
        for (int off = 1; off < 32; off <<= 1)
            sum += __shfl_xor_sync(0xffffffffu, sum, off);
        float mu = sum * (1.0f / HDIM);
        float sq = 0.0f;
#pragma unroll
        for (int q = 0; q < 8; q++) { float d = x[q] - mu; sq += d * d; }
#pragma unroll
        for (int off = 1; off < 32; off <<= 1)
            sq += __shfl_xor_sync(0xffffffffu, sq, off);
        float inv = rsqrtf(sq * (1.0f / HDIM) + 1e-5f);

        int cell = c0 + R0 + rr;
        int rg = regions[cell];
        float wn = expf(g_w[cell] - g_m[rg]) / g_denom[rg];
#pragma unroll
        for (int q = 0; q < 8; q++) {
            float y = ((x[q] - mu) * inv * gv[q] + bev[q]) * wn;
            atomicAdd(&g_agg[(size_t)rg * HDIM + C0 + q], y);
        }
    }
}

__device__ __forceinline__ float block_sum256(float v, float* sbuf) {
#pragma unroll
    for (int off = 1; off < 32; off <<= 1)
        v += __shfl_xor_sync(0xffffffffu, v, off);
    int w = threadIdx.x >> 5;
    if ((threadIdx.x & 31) == 0) sbuf[w] = v;
    __syncthreads();
    float t = 0.0f;
#pragma unroll
    for (int i = 0; i < 8; i++) t += sbuf[i];
    __syncthreads();
    return t;
}

__global__ __launch_bounds__(256) void region_up_kernel(
    const float* __restrict__ w_up, const float* __restrict__ b_up,
    const float* __restrict__ g_up, const float* __restrict__ be_up,
    const float* __restrict__ z_fused, const float* __restrict__ raw_rw,
    float* __restrict__ out_fused)
{
    __shared__ float a_s[HDIM];
    __shared__ float sbuf[8];
    int r = blockIdx.x, tid = threadIdx.x;
    a_s[tid] = g_agg[(size_t)r * HDIM + tid];
    __syncthreads();
    float acc0 = b_up[tid], acc1 = b_up[tid + 256];
    for (int k = 0; k < HDIM; k++) {
        float a = a_s[k];
        acc0 = fmaf(a, w_up[(size_t)k * DDIM + tid], acc0);
        acc1 = fmaf(a, w_up[(size_t)k * DDIM + tid + 256], acc1);
    }
    float x0 = gelu_exact(acc0), x1 = gelu_exact(acc1);
    float mu = block_sum256(x0 + x1, sbuf) * (1.0f / DDIM);
    float d0 = x0 - mu, d1 = x1 - mu;
    float var = block_sum256(d0 * d0 + d1 * d1, sbuf) * (1.0f / DDIM);
    float inv = rsqrtf(var + 1e-5f);
    float u0 = d0 * inv * g_up[tid] + be_up[tid];
    float u1 = d1 * inv * g_up[tid + 256] + be_up[tid + 256];
    bool present = g_cnt[r] > 0.0f;
    float zf0 = z_fused[(size_t)r * DDIM + tid];
    float zf1 = z_fused[(size_t)r * DDIM + tid + 256];
    float s0 = present ? u0 : zf0;
    float s1 = present ? u1 : zf1;
    g_upd[(size_t)r * DDIM + tid] = s0;
    g_upd[(size_t)r * DDIM + tid + 256] = s1;
    float rw = 1.0f / (1.0f + expf(-__ldg(raw_rw)));
    out_fused[(size_t)r * DDIM + tid]       = rw * s0 + (1.0f - rw) * zf0;
    out_fused[(size_t)r * DDIM + tid + 256] = rw * s1 + (1.0f - rw) * zf1;
}

__global__ __launch_bounds__(256) void region_hb_kernel(
    const float* __restrict__ w_d1, const float* __restrict__ b_d1,
    const float* __restrict__ g_d1, const float* __restrict__ be_d1)
{
    __shared__ float z_s[DDIM];
    __shared__ float sbuf[8];
    int r = blockIdx.x, tid = threadIdx.x;
    z_s[tid] = g_upd[(size_t)r * DDIM + tid];
    z_s[tid + 256] = g_upd[(size_t)r * DDIM + tid + 256];
    __syncthreads();
    float acc = b_d1[tid];
    for (int k = 0; k < DDIM; k++)
        acc = fmaf(z_s[k], w_d1[(size_t)k * HDIM + tid], acc);
    float x = gelu_exact(acc);
    float mu = block_sum256(x, sbuf) * (1.0f / HDIM);
    float d = x - mu;
    float var = block_sum256(d * d, sbuf) * (1.0f / HDIM);
    float inv = rsqrtf(var + 1e-5f);
    g_hb[(size_t)r * HDIM + tid] = d * inv * g_d1[tid] + be_d1[tid];
}

__global__ __launch_bounds__(256) void region_bcast_kernel(
    const float* __restrict__ w_d2, const float* __restrict__ b_d2)
{
    __shared__ float h_s[HDIM];
    int r = blockIdx.x, tid = threadIdx.x;
    h_s[tid] = g_hb[(size_t)r * HDIM + tid];
    __syncthreads();
    float acc0 = b_d2[tid], acc1 = b_d2[tid + 256];
    for (int k = 0; k < HDIM; k++) {
        float h = h_s[k];
        acc0 = fmaf(h, w_d2[(size_t)k * DDIM + tid], acc0);
        acc1 = fmaf(h, w_d2[(size_t)k * DDIM + tid + 256], acc1);
    }
    g_bcast[(size_t)r * DDIM + tid] = acc0;
    g_bcast[(size_t)r * DDIM + tid + 256] = acc1;
}

extern "C" void kernel_launch(void* const* d_in, const int* in_sizes, int n_in,
                              void* d_out, int out_size) {
    const float* z_local = (const float*)d_in[0];
    const float* z_fused = (const float*)d_in[1];
    const int*   regions = (const int*)d_in[2];
    const float* protos  = (const float*)d_in[3];
    const float* temp    = (const float*)d_in[4];
    const float* raw_rw  = (const float*)d_in[5];
    const float* w_ua = (const float*)d_in[6];
    const float* b_ua = (const float*)d_in[7];
    const float* g_ua = (const float*)d_in[8];
    const float* be_ua = (const float*)d_in[9];
    const float* w_up = (const float*)d_in[10];
    const float* b_up = (const float*)d_in[11];
    const float* g_up = (const float*)d_in[12];
    const float* be_up = (const float*)d_in[13];
    const float* w_d1 = (const float*)d_in[14];
    const float* b_d1 = (const float*)d_in[15];
    const float* g_d1 = (const float*)d_in[16];
    const float* be_d1 = (const float*)d_in[17];
    const float* w_d2 = (const float*)d_in[18];
    const float* b_d2 = (const float*)d_in[19];

    float* out_local = (float*)d_out;
    float* out_fused = out_local + (size_t)NCELLS * DDIM;

    cudaFuncSetAttribute(pass_tc<0>, cudaFuncAttributeMaxDynamicSharedMemorySize, SM_TOTAL);
    cudaFuncSetAttribute(pass_tc<1>, cudaFuncAttributeMaxDynamicSharedMemorySize, SM_TOTAL);

    init_kernel<<<(RREG * HDIM + 255) / 256, 256>>>();
    pass_tc<0><<<NCELLS / PT_M, 256, SM_TOTAL>>>(z_local, protos, regions, temp, raw_rw, nullptr);
    seg_sum_kernel<<<NCELLS / 256, 256>>>(regions);
    h_agg_kernel<<<NCELLS / HM, 256>>>(z_local, w_ua, b_ua, g_ua, be_ua, regions);
    region_up_kernel<<<RREG, 256>>>(w_up, b_up, g_up, be_up, z_fused, raw_rw, out_fused);
    region_hb_kernel<<<RREG, 256>>>(w_d1, b_d1, g_d1, be_d1);
    region_bcast_kernel<<<RREG, 256>>>(w_d2, b_d2);
    pass_tc<1><<<NCELLS / PT_M, 256, SM_TOTAL>>>(z_local, nullptr, regions, temp, raw_rw, out_local);
}

// round 7
// speedup vs baseline: 2.0407x; 1.0484x over previous
#include <cuda_runtime.h>
#include <math.h>
#include <stdint.h>

#define NCELLS 131072
#define RREG   512
#define DDIM   512
#define HDIM   256

typedef unsigned long long ull;
typedef unsigned int u32;

#if defined(__CUDA_ARCH_FEAT_SM103_ALL) || defined(__CUDA_ARCH_FEAT_SM100_ALL) || defined(__CUDA_ARCH_FEAT_SM101_ALL)
#define HAS_TCGEN05 1
#else
#define HAS_TCGEN05 0
#endif

__device__ float g_w[NCELLS];
__device__ float g_m[RREG];
__device__ float g_denom[RREG];
__device__ float g_cnt[RREG];
__device__ float g_agg[RREG * HDIM];
__device__ float g_upd[RREG * DDIM];
__device__ float g_hb[RREG * HDIM];
__device__ float g_bcast[RREG * DDIM];
// hi/lo tf32 split operands (B matrices of the tensor-core GEMMs)
__device__ float g_protos_hi[RREG * DDIM];
__device__ float g_protos_lo[RREG * DDIM];
__device__ float g_upd_hi[RREG * DDIM];
__device__ float g_upd_lo[RREG * DDIM];
__device__ float g_wua_hi[HDIM * DDIM];   // transposed: [H][D]
__device__ float g_wua_lo[HDIM * DDIM];

__device__ __forceinline__ float gelu_exact(float x) {
    return 0.5f * x * (1.0f + erff(x * 0.70710678118654752440f));
}
__device__ __forceinline__ ull pack2(float a) {
    ull r; asm("mov.b64 %0, {%1,%1};" : "=l"(r) : "f"(a)); return r;
}
__device__ __forceinline__ float2 unpack2(ull v) {
    float2 r; asm("mov.b64 {%0,%1}, %2;" : "=f"(r.x), "=f"(r.y) : "l"(v)); return r;
}
__device__ __forceinline__ void fma2(ull &d, ull a, ull b) {
    asm("fma.rn.f32x2 %0, %1, %2, %3;" : "=l"(d) : "l"(a), "l"(b), "l"(d));
}
__device__ __forceinline__ float tf32f(float x) {   // valid on base sm_103 too
    u32 u; asm("cvt.rna.tf32.f32 %0, %1;" : "=r"(u) : "f"(x)); return __uint_as_float(u);
}

#if HAS_TCGEN05
// ---------------- tcgen05 helpers (compiled only on 'a' targets) -------------
__device__ __forceinline__ u32 smem_u32(const void* p) {
    u32 a; asm("{ .reg .u64 t; cvta.to.shared.u64 t, %1; cvt.u32.u64 %0, t; }" : "=r"(a) : "l"(p));
    return a;
}
__device__ __forceinline__ bool elect_one() {
    u32 pred;
    asm volatile("{\n\t.reg .pred p;\n\telect.sync _|p, 0xFFFFFFFF;\n\tselp.b32 %0, 1, 0, p;\n\t}" : "=r"(pred));
    return pred != 0;
}
__device__ __forceinline__ void mbar_init(u32 addr, u32 cnt) {
    asm volatile("mbarrier.init.shared.b64 [%0], %1;" :: "r"(addr), "r"(cnt) : "memory");
}
__device__ __forceinline__ void mbar_inval(u32 addr) {
    asm volatile("mbarrier.inval.shared.b64 [%0];" :: "r"(addr) : "memory");
}
__device__ __forceinline__ void mbar_wait(u32 addr, u32 parity) {
    asm volatile(
        "{\n\t.reg .pred P;\n\t"
        "WL_%=:\n\t"
        "mbarrier.try_wait.parity.acquire.cta.shared::cta.b64 P, [%0], %1, 0x989680;\n\t"
        "@P bra.uni WD_%=;\n\t"
        "bra.uni WL_%=;\n\t"
        "WD_%=:\n\t}"
        :: "r"(addr), "r"(parity) : "memory");
}
__device__ __forceinline__ void tc_alloc(u32 smem_dst, u32 ncols) {
    asm volatile("tcgen05.alloc.cta_group::1.sync.aligned.shared::cta.b32 [%0], %1;"
                 :: "r"(smem_dst), "r"(ncols) : "memory");
}
__device__ __forceinline__ void tc_relinquish() {
    asm volatile("tcgen05.relinquish_alloc_permit.cta_group::1.sync.aligned;");
}
__device__ __forceinline__ void tc_dealloc(u32 tmem, u32 ncols) {
    asm volatile("tcgen05.dealloc.cta_group::1.sync.aligned.b32 %0, %1;" :: "r"(tmem), "r"(ncols));
}
__device__ __forceinline__ void tc_commit(u32 mbar) {
    asm volatile("tcgen05.commit.cta_group::1.mbarrier::arrive::one.shared::cluster.b64 [%0];"
                 :: "r"(mbar) : "memory");
}
__device__ __forceinline__ void tc_fence_after() {
    asm volatile("tcgen05.fence::after_thread_sync;" ::: "memory");
}
__device__ __forceinline__ void fence_proxy() {
    asm volatile("fence.proxy.async.shared::cta;" ::: "memory");
}
__device__ __forceinline__ void mma_tf32_ss(u32 d, ull ad, ull bd, u32 idesc, bool acc) {
    u32 e = acc ? 1u : 0u;
    asm volatile(
        "{\n\t.reg .pred p;\n\tsetp.ne.u32 p, %5, 0;\n\t"
        "tcgen05.mma.cta_group::1.kind::tf32 [%0], %1, %2, %3, {%4, %4, %4, %4}, p;\n\t}"
        :: "r"(d), "l"(ad), "l"(bd), "r"(idesc), "r"(0u), "r"(e) : "memory");
}
__device__ __forceinline__ void tc_wait_ld() {
    asm volatile("tcgen05.wait::ld.sync.aligned;" ::: "memory");
}
__device__ __forceinline__ void tc_wait_st() {
    asm volatile("tcgen05.wait::st.sync.aligned;" ::: "memory");
}
__device__ __forceinline__ void ldtm32(u32* r, u32 tmem_addr) {
    asm volatile(
        "tcgen05.ld.sync.aligned.32x32b.x32.b32 "
        "{%0, %1, %2, %3, %4, %5, %6, %7, "
        " %8, %9, %10, %11, %12, %13, %14, %15, "
        " %16, %17, %18, %19, %20, %21, %22, %23, "
        " %24, %25, %26, %27, %28, %29, %30, %31}, [%32];"
        : "=r"(r[0]), "=r"(r[1]), "=r"(r[2]), "=r"(r[3]),
          "=r"(r[4]), "=r"(r[5]), "=r"(r[6]), "=r"(r[7]),
          "=r"(r[8]), "=r"(r[9]), "=r"(r[10]), "=r"(r[11]),
          "=r"(r[12]), "=r"(r[13]), "=r"(r[14]), "=r"(r[15]),
          "=r"(r[16]), "=r"(r[17]), "=r"(r[18]), "=r"(r[19]),
          "=r"(r[20]), "=r"(r[21]), "=r"(r[22]), "=r"(r[23]),
          "=r"(r[24]), "=r"(r[25]), "=r"(r[26]), "=r"(r[27]),
          "=r"(r[28]), "=r"(r[29]), "=r"(r[30]), "=r"(r[31])
        : "r"(tmem_addr));
}
__device__ __forceinline__ void sttm32(u32 tmem_addr, const u32* r) {
    asm volatile(
        "tcgen05.st.sync.aligned.32x32b.x32.b32 [%0], "
        "{%1, %2, %3, %4, %5, %6, %7, %8, "
        " %9, %10, %11, %12, %13, %14, %15, %16, "
        " %17, %18, %19, %20, %21, %22, %23, %24, "
        " %25, %26, %27, %28, %29, %30, %31, %32};"
        :: "r"(tmem_addr),
           "r"(r[0]),  "r"(r[1]),  "r"(r[2]),  "r"(r[3]),
           "r"(r[4]),  "r"(r[5]),  "r"(r[6]),  "r"(r[7]),
           "r"(r[8]),  "r"(r[9]),  "r"(r[10]), "r"(r[11]),
           "r"(r[12]), "r"(r[13]), "r"(r[14]), "r"(r[15]),
           "r"(r[16]), "r"(r[17]), "r"(r[18]), "r"(r[19]),
           "r"(r[20]), "r"(r[21]), "r"(r[22]), "r"(r[23]),
           "r"(r[24]), "r"(r[25]), "r"(r[26]), "r"(r[27]),
           "r"(r[28]), "r"(r[29]), "r"(r[30]), "r"(r[31])
        : "memory");
}
__device__ __forceinline__ ull smem_desc(u32 base) {
    return ((ull)2 << 61) | ((ull)1 << 46) | ((ull)64 << 32) | ((ull)1 << 16)
         | ((ull)(base >> 4) & 0x3FFF);
}
#define SWZ(x) ((x) ^ ((((u32)(x)) >> 3) & 0x70))
#endif  // HAS_TCGEN05

__global__ void init_kernel() {
    int i = blockIdx.x * blockDim.x + threadIdx.x;
    if (i < RREG * HDIM) g_agg[i] = 0.0f;
    if (i < RREG) { g_m[i] = 0.0f; g_denom[i] = 0.0f; g_cnt[i] = 0.0f; }
}

// hi/lo split of protos + transposed hi/lo split of w_ua
__global__ void prep_kernel(const float* __restrict__ protos, const float* __restrict__ w_ua) {
    int i = blockIdx.x * blockDim.x + threadIdx.x;
    if (i < RREG * DDIM) {
        float v = protos[i];
        float h = tf32f(v);
        g_protos_hi[i] = h; g_protos_lo[i] = v - h;
    }
    if (i < HDIM * DDIM) {
        int j = i / DDIM, k = i % DDIM;
        float v = w_ua[k * HDIM + j];
        float h = tf32f(v);
        g_wua_hi[i] = h; g_wua_lo[i] = v - h;
    }
}

// ---------------- pass kernel: scores + fused row softmax --------------------
#define PT_M     128
#define PT_KC    32
#define PT_STEPS ((DDIM / PT_KC) * 4)
#define TILE_B   16384
#define SM_CTRL  2048
#define SM_TOTAL (SM_CTRL + 8 * TILE_B)
#define TOFF(i)  (SM_CTRL + (i) * TILE_B)
#define IDESC_TF32 ((1u << 4) | (2u << 7) | (2u << 10) | ((128u / 8) << 17) | ((128u / 16) << 24))

template <int MODE>
__global__ __launch_bounds__(256) void pass_tc(
    const float* __restrict__ A, const float* __restrict__ Bext,
    const int* __restrict__ regions, const float* __restrict__ temp,
    const float* __restrict__ raw_rw, float* __restrict__ out)
{
    extern __shared__ __align__(1024) char smem[];
    const int tid = threadIdx.x;
    const int c0 = blockIdx.x * PT_M;
    const float inv_t = 1.0f / __ldg(temp);

    int*   reg_s = (int*)(smem + 32);
    float* w_s   = (float*)(smem + 544);

#if HAS_TCGEN05
    // ================= tcgen05 3xTF32 path =================
    const float* Bh = (MODE == 0) ? (const float*)g_protos_hi : (const float*)g_upd_hi;
    const float* Bl = (MODE == 0) ? (const float*)g_protos_lo : (const float*)g_upd_lo;
    const u32 sb = smem_u32(smem);
    const int wid = tid >> 5;
    const int lid = tid & 31;

    if (wid == 0) tc_alloc(sb + 0, 512); else tc_relinquish();
    if (tid == 0) { mbar_init(sb + 8, 1); mbar_init(sb + 16, 1); }
    if (tid < PT_M) reg_s[tid] = regions[c0 + tid];
    __syncthreads();
    u32 tmem;
    asm volatile("ld.shared.b32 %0, [%1];" : "=r"(tmem) : "r"(sb + 0));

    const int lrow = tid >> 1;
    const int lc0  = (tid & 1) * 4;

    int ph0 = 0, ph1 = 0;
    for (int t = 0; t < PT_STEPS; ++t) {
        if (t >= 2) {
            if (t & 1) { mbar_wait(sb + 16, ph1); ph1 ^= 1; }
            else       { mbar_wait(sb + 8,  ph0); ph0 ^= 1; }
        }
        const int s = t & 1, n = t & 3, k = t >> 2;
        {   // B: pure copy from precomputed hi/lo
            const size_t boff = (size_t)(n * 128 + lrow) * DDIM + k * PT_KC + lc0 * 4;
            char* bh = smem + TOFF(4 + 2 * s);
            char* bl = smem + TOFF(5 + 2 * s);
#pragma unroll
            for (int i = 0; i < 4; ++i) {
                float4 vh = *(const float4*)(Bh + boff + i * 4);
                float4 vl = *(const float4*)(Bl + boff + i * 4);
                u32 off = SWZ(lrow * 128 + (lc0 + i) * 16);
                *(float4*)(bh + off) = vh;
                *(float4*)(bl + off) = vl;
            }
        }
        if (n == 0) {   // A: convert (hi = cvt.rna, lo = raw residual)
            const float* src = A + (size_t)(c0 + lrow) * DDIM + k * PT_KC + lc0 * 4;
            char* ah = smem + TOFF(0 + 2 * (k & 1));
            char* al = smem + TOFF(1 + 2 * (k & 1));
#pragma unroll
            for (int i = 0; i < 4; ++i) {
                float4 v = *(const float4*)(src + i * 4);
                float4 h, l;
                h.x = tf32f(v.x); l.x = v.x - h.x;
                h.y = tf32f(v.y); l.y = v.y - h.y;
                h.z = tf32f(v.z); l.z = v.z - h.z;
                h.w = tf32f(v.w); l.w = v.w - h.w;
                u32 off = SWZ(lrow * 128 + (lc0 + i) * 16);
                *(float4*)(ah + off) = h;
                *(float4*)(al + off) = l;
            }
        }
        __syncthreads();
        if (wid == 0 && elect_one()) {
            fence_proxy();
            ull adh = smem_desc(sb + TOFF(0 + 2 * (k & 1)));
            ull adl = smem_desc(sb + TOFF(1 + 2 * (k & 1)));
            ull bdh = smem_desc(sb + TOFF(4 + 2 * s));
            ull bdl = smem_desc(sb + TOFF(5 + 2 * s));
            u32 d = tmem + n * 128;
#pragma unroll
            for (int ks = 0; ks < 4; ++ks) {
                mma_tf32_ss(d, adh + ks * 2, bdh + ks * 2, IDESC_TF32, !(k == 0 && ks == 0));
                mma_tf32_ss(d, adh + ks * 2, bdl + ks * 2, IDESC_TF32, true);
                mma_tf32_ss(d, adl + ks * 2, bdh + ks * 2, IDESC_TF32, true);
            }
            tc_commit(sb + 8 + s * 8);
        }
    }
    mbar_wait(sb + 8, ph0);
    mbar_wait(sb + 16, ph1);
    __syncthreads();
    tc_fence_after();

    if (wid < 4) {
        const int row = wid * 32 + lid;
        const int jown = reg_s[row];
        const int jch = jown >> 5, jidx = jown & 31;
        float m = -3.4e38f, l = 0.0f, sown = 0.0f;
#pragma unroll
        for (int ch = 0; ch < 16; ++ch) {
            u32 r[32];
            ldtm32(r, tmem + ch * 32);
            tc_wait_ld();
            float sv[32];
#pragma unroll
            for (int q = 0; q < 32; ++q) sv[q] = __uint_as_float(r[q]) * inv_t;
            float cmax = sv[0];
#pragma unroll
            for (int q = 1; q < 32; ++q) cmax = fmaxf(cmax, sv[q]);
            float mn = fmaxf(m, cmax);
            float p = 0.0f;
#pragma unroll
            for (int q = 0; q < 32; ++q) p += expf(sv[q] - mn);
            l = l * expf(m - mn) + p;
            m = mn;
            if (ch == jch) {
#pragma unroll
                for (int q = 0; q < 32; ++q) sown = (q == jidx) ? sv[q] : sown;
            }
        }
        float wv = expf(sown - m) / l;
        if (MODE == 0) {
            g_w[c0 + row] = wv;
            atomicMax((int*)&g_m[jown], __float_as_int(wv));   // wv > 0 always
        } else {
            w_s[row] = wv;
        }
    }
    __syncthreads();
    if (tid == 0) { mbar_inval(sb + 8); mbar_inval(sb + 16); }
    __syncthreads();
    if (wid == 0) tc_dealloc(tmem, 512);

#else
    // ================= f32x2 fallback path (base sm_103 PTX; never selected) =
    const float* B = (MODE == 0) ? Bext : (const float*)g_upd;
    float* As0 = (float*)(smem + SM_CTRL);
    float* Bs0 = As0 + 2 * 16 * 132;
    const int tx = tid & 15;
    const int ty = tid >> 4;
    const int R0 = ty * 8;
    if (tid < PT_M) reg_s[tid] = regions[c0 + tid];

    const int lrow = tid >> 2;
    const int lseg = (tid & 3) * 4;
    float4 pa0, pa1, pb0, pb1;
    const int NT = (RREG / 128) * (DDIM / 16);

    auto LD = [&](int u) {
        const int k0  = (u & 31) * 16;
        const int col0 = (u >> 5) * 128;
        const float* Ap = A + (size_t)(c0 + lrow) * DDIM + k0 + lseg;
        pa0 = *reinterpret_cast<const float4*>(Ap);
        pa1 = *reinterpret_cast<const float4*>(Ap + (size_t)64 * DDIM);
        const float* Bp = B + (size_t)(col0 + lrow) * DDIM + k0 + lseg;
        pb0 = *reinterpret_cast<const float4*>(Bp);
        pb1 = *reinterpret_cast<const float4*>(Bp + (size_t)64 * DDIM);
    };
    auto ST = [&](int b) {
        float* As = As0 + b * 16 * 132;
        float* Bs = Bs0 + b * 16 * 132;
        As[(lseg + 0) * 132 + lrow] = pa0.x; As[(lseg + 1) * 132 + lrow] = pa0.y;
        As[(lseg + 2) * 132 + lrow] = pa0.z; As[(lseg + 3) * 132 + lrow] = pa0.w;
        As[(lseg + 0) * 132 + lrow + 64] = pa1.x; As[(lseg + 1) * 132 + lrow + 64] = pa1.y;
        As[(lseg + 2) * 132 + lrow + 64] = pa1.z; As[(lseg + 3) * 132 + lrow + 64] = pa1.w;
        Bs[(lseg + 0) * 132 + lrow] = pb0.x; Bs[(lseg + 1) * 132 + lrow] = pb0.y;
        Bs[(lseg + 2) * 132 + lrow] = pb0.z; Bs[(lseg + 3) * 132 + lrow] = pb0.w;
        Bs[(lseg + 0) * 132 + lrow + 64] = pb1.x; Bs[(lseg + 1) * 132 + lrow + 64] = pb1.y;
        Bs[(lseg + 2) * 132 + lrow + 64] = pb1.z; Bs[(lseg + 3) * 132 + lrow + 64] = pb1.w;
    };

    float m_run[8], l_run[8], s_own[8];
#pragma unroll
    for (int r = 0; r < 8; r++) { m_run[r] = -3.4e38f; l_run[r] = 0.0f; s_own[r] = 0.0f; }

    ull acc[8][4];
#pragma unroll
    for (int r = 0; r < 8; r++)
#pragma unroll
        for (int c = 0; c < 4; c++) acc[r][c] = 0ull;

    LD(0); ST(0); LD(1);
    __syncthreads();

    for (int u = 0; u < NT; ++u) {
        const int b = u & 1;
        if (u + 1 < NT) ST(b ^ 1);
        if (u + 2 < NT) LD(u + 2);
        const float* As = As0 + b * 16 * 132;
        const float* Bs = Bs0 + b * 16 * 132;
#pragma unroll
        for (int kk = 0; kk < 16; ++kk) {
            float4 a0 = *reinterpret_cast<const float4*>(&As[kk * 132 + R0]);
            float4 a1 = *reinterpret_cast<const float4*>(&As[kk * 132 + R0 + 4]);
            ulonglong2 bq0 = *reinterpret_cast<const ulonglong2*>(&Bs[kk * 132 + tx * 8]);
            ulonglong2 bq1 = *reinterpret_cast<const ulonglong2*>(&Bs[kk * 132 + tx * 8 + 4]);
            ull ap[8] = { pack2(a0.x), pack2(a0.y), pack2(a0.z), pack2(a0.w),
                          pack2(a1.x), pack2(a1.y), pack2(a1.z), pack2(a1.w) };
            ull bb[4] = { bq0.x, bq0.y, bq1.x, bq1.y };
#pragma unroll
            for (int r = 0; r < 8; r++) {
                fma2(acc[r][0], ap[r], bb[0]);
                fma2(acc[r][1], ap[r], bb[1]);
                fma2(acc[r][2], ap[r], bb[2]);
                fma2(acc[r][3], ap[r], bb[3]);
            }
        }
        if ((u & 31) == 31) {
            const int col0 = (u >> 5) * 128;
#pragma unroll
            for (int rr = 0; rr < 8; ++rr) {
                float s[8];
#pragma unroll
                for (int c = 0; c < 4; c++) {
                    float2 f = unpack2(acc[rr][c]);
                    s[2 * c] = f.x * inv_t; s[2 * c + 1] = f.y * inv_t;
                }
                float tmax = s[0];
#pragma unroll
                for (int q = 1; q < 8; q++) tmax = fmaxf(tmax, s[q]);
#pragma unroll
                for (int off = 1; off < 16; off <<= 1)
                    tmax = fmaxf(tmax, __shfl_xor_sync(0xffffffffu, tmax, off));
                float mo = m_run[rr];
                float mn = fmaxf(mo, tmax);
                float p = 0.0f;
#pragma unroll
                for (int q = 0; q < 8; q++) p += expf(s[q] - mn);
#pragma unroll
                for (int off = 1; off < 16; off <<= 1)
                    p += __shfl_xor_sync(0xffffffffu, p, off);
                l_run[rr] = l_run[rr] * expf(mo - mn) + p;
                m_run[rr] = mn;
                int d = reg_s[R0 + rr] - col0;
                if ((unsigned)d < 128u && (d >> 3) == tx) s_own[rr] += s[d & 7];
#pragma unroll
                for (int c = 0; c < 4; c++) acc[rr][c] = 0ull;
            }
        }
        __syncthreads();
    }

#pragma unroll
    for (int rr = 0; rr < 8; ++rr) {
        float so = s_own[rr];
#pragma unroll
        for (int off = 1; off < 16; off <<= 1)
            so += __shfl_xor_sync(0xffffffffu, so, off);
        float wv = expf(so - m_run[rr]) / l_run[rr];
        if (tx == 0) {
            if (MODE == 0) {
                g_w[c0 + R0 + rr] = wv;
                atomicMax((int*)&g_m[reg_s[R0 + rr]], __float_as_int(wv));
            } else {
                w_s[R0 + rr] = wv;
            }
        }
    }
    __syncthreads();
#endif

    if (MODE == 1) {
        float xr = __ldg(raw_rw);
        float rw = 1.0f / (1.0f + expf(-xr));
        float orw = 1.0f - rw;
        for (int idx = tid; idx < PT_M * (DDIM / 4); idx += 256) {
            int row = idx >> 7;
            int c4 = idx & 127;
            int rg = reg_s[row];
            float wt = w_s[row];
            float4 bc = *reinterpret_cast<const float4*>(g_bcast + (size_t)rg * DDIM + c4 * 4);
            float4 zl = *reinterpret_cast<const float4*>(A + (size_t)(c0 + row) * DDIM + c4 * 4);
            float4 o;
            o.x = rw * (bc.x * wt) + orw * zl.x;
            o.y = rw * (bc.y * wt) + orw * zl.y;
            o.z = rw * (bc.z * wt) + orw * zl.z;
            o.w = rw * (bc.w * wt) + orw * zl.w;
            *reinterpret_cast<float4*>(out + (size_t)(c0 + row) * DDIM + c4 * 4) = o;
        }
    }
}

__global__ void seg_sum_kernel(const int* __restrict__ regions) {
    int i = blockIdx.x * blockDim.x + threadIdx.x;
    if (i < NCELLS) {
        int r = regions[i];
        float e = expf(g_w[i] - g_m[r]);
        atomicAdd(&g_denom[r], e);
        atomicAdd(&g_cnt[r], 1.0f);
    }
}

// ---------------- h_agg on tensor cores: M=128, N=256 (2 tiles), K=512 -------
#define HSM_CTRL  4096
#define HSM_TOTAL (HSM_CTRL + 8 * TILE_B)
#define HTOFF(i)  (HSM_CTRL + (i) * TILE_B)

__global__ __launch_bounds__(256) void h_agg_tc(
    const float* __restrict__ A, const float* __restrict__ w_ua,
    const float* __restrict__ b_ua, const float* __restrict__ g_ua,
    const float* __restrict__ be_ua, const int* __restrict__ regions)
{
    extern __shared__ __align__(1024) char smem[];
    const int tid = threadIdx.x;
    const int c0 = blockIdx.x * PT_M;
    int*   reg_s = (int*)(smem + 32);
    float* b_s   = (float*)(smem + 1024);
    float* g_s   = (float*)(smem + 2048);
    float* be_s  = (float*)(smem + 3072);

#if HAS_TCGEN05
    const u32 sb = smem_u32(smem);
    const int wid = tid >> 5, lid = tid & 31;
    if (wid == 0) tc_alloc(sb + 0, 512); else tc_relinquish();
    if (tid == 0) { mbar_init(sb + 8, 1); mbar_init(sb + 16, 1); }
    if (tid < PT_M) reg_s[tid] = regions[c0 + tid];
    b_s[tid]  = b_ua[tid];
    g_s[tid]  = g_ua[tid];
    be_s[tid] = be_ua[tid];
    __syncthreads();
    u32 tmem;
    asm volatile("ld.shared.b32 %0, [%1];" : "=r"(tmem) : "r"(sb + 0));

    const int lrow = tid >> 1;
    const int lc0  = (tid & 1) * 4;

    int ph0 = 0, ph1 = 0;
    const int NSTEP = 32;   // 16 k-chunks x 2 n-tiles
    for (int t = 0; t < NSTEP; ++t) {
        if (t >= 2) {
            if (t & 1) { mbar_wait(sb + 16, ph1); ph1 ^= 1; }
            else       { mbar_wait(sb + 8,  ph0); ph0 ^= 1; }
        }
        const int s = t & 1, n = t & 1, k = t >> 1;
        {   // B copy from transposed w_ua hi/lo
            const size_t boff = (size_t)(n * 128 + lrow) * DDIM + k * PT_KC + lc0 * 4;
            char* bh = smem + HTOFF(4 + 2 * s);
            char* bl = smem + HTOFF(5 + 2 * s);
#pragma unroll
            for (int i = 0; i < 4; ++i) {
                float4 vh = *(const float4*)((const float*)g_wua_hi + boff + i * 4);
                float4 vl = *(const float4*)((const float*)g_wua_lo + boff + i * 4);
                u32 off = SWZ(lrow * 128 + (lc0 + i) * 16);
                *(float4*)(bh + off) = vh;
                *(float4*)(bl + off) = vl;
            }
        }
        if (n == 0) {   // A convert
            const float* src = A + (size_t)(c0 + lrow) * DDIM + k * PT_KC + lc0 * 4;
            char* ah = smem + HTOFF(0 + 2 * (k & 1));
            char* al = smem + HTOFF(1 + 2 * (k & 1));
#pragma unroll
            for (int i = 0; i < 4; ++i) {
                float4 v = *(const float4*)(src + i * 4);
                float4 h, l;
                h.x = tf32f(v.x); l.x = v.x - h.x;
                h.y = tf32f(v.y); l.y = v.y - h.y;
                h.z = tf32f(v.z); l.z = v.z - h.z;
                h.w = tf32f(v.w); l.w = v.w - h.w;
                u32 off = SWZ(lrow * 128 + (lc0 + i) * 16);
                *(float4*)(ah + off) = h;
                *(float4*)(al + off) = l;
            }
        }
        __syncthreads();
        if (wid == 0 && elect_one()) {
            fence_proxy();
            ull adh = smem_desc(sb + HTOFF(0 + 2 * (k & 1)));
            ull adl = smem_desc(sb + HTOFF(1 + 2 * (k & 1)));
            ull bdh = smem_desc(sb + HTOFF(4 + 2 * s));
            ull bdl = smem_desc(sb + HTOFF(5 + 2 * s));
            u32 d = tmem + n * 128;
#pragma unroll
            for (int ks = 0; ks < 4; ++ks) {
                mma_tf32_ss(d, adh + ks * 2, bdh + ks * 2, IDESC_TF32, !(k == 0 && ks == 0));
                mma_tf32_ss(d, adh + ks * 2, bdl + ks * 2, IDESC_TF32, true);
                mma_tf32_ss(d, adl + ks * 2, bdh + ks * 2, IDESC_TF32, true);
            }
            tc_commit(sb + 8 + s * 8);
        }
    }
    mbar_wait(sb + 8, ph0);
    mbar_wait(sb + 16, ph1);
    __syncthreads();
    tc_fence_after();

    if (wid < 4) {
        const int row = wid * 32 + lid;
        // phase 1: gelu(acc + b), accumulate sum/sumsq, park x in TMEM cols 256+
        float sum = 0.0f, sq = 0.0f;
#pragma unroll
        for (int ch = 0; ch < 8; ++ch) {
            u32 r[32];
            ldtm32(r, tmem + ch * 32);
            tc_wait_ld();
            u32 xb[32];
#pragma unroll
            for (int q = 0; q < 32; ++q) {
                float x = gelu_exact(__uint_as_float(r[q]) + b_s[ch * 32 + q]);
                sum += x; sq += x * x;
                xb[q] = __float_as_uint(x);
            }
            sttm32(tmem + 256 + ch * 32 + ((u32)wid << 21), xb);
        }
        tc_wait_st();
        float mu  = sum * (1.0f / HDIM);
        float var = fmaxf(sq * (1.0f / HDIM) - mu * mu, 0.0f);
        float inv = rsqrtf(var + 1e-5f);
        const int cell = c0 + row;
        const int rg = reg_s[row];
        float wn = expf(g_w[cell] - g_m[rg]) / g_denom[rg];
        float* aggp = g_agg + (size_t)rg * HDIM;
        // phase 2: normalize + weighted atomic accumulate
#pragma unroll
        for (int ch = 0; ch < 8; ++ch) {
            u32 r[32];
            ldtm32(r, tmem + 256 + ch * 32);
            tc_wait_ld();
#pragma unroll
            for (int q = 0; q < 32; ++q) {
                int j = ch * 32 + q;
                float y = ((__uint_as_float(r[q]) - mu) * inv * g_s[j] + be_s[j]) * wn;
                atomicAdd(aggp + j, y);
            }
        }
    }
    __syncthreads();
    if (tid == 0) { mbar_inval(sb + 8); mbar_inval(sb + 16); }
    __syncthreads();
    if (wid == 0) tc_dealloc(tmem, 512);

#else
    // naive fallback (never selected on GB300; sm_103a cubin exists)
    (void)reg_s; (void)b_s; (void)g_s; (void)be_s;
    if (tid < PT_M) {
        int row = c0 + tid;
        int rg = regions[row];
        float wn = expf(g_w[row] - g_m[rg]) / g_denom[rg];
        float sum = 0.0f, sq = 0.0f;
        for (int j = 0; j < HDIM; ++j) {
            float acc = b_ua[j];
            for (int k = 0; k < DDIM; ++k)
                acc += A[(size_t)row * DDIM + k] * w_ua[(size_t)k * HDIM + j];
            float x = gelu_exact(acc);
            sum += x; sq += x * x;
        }
        float mu = sum / HDIM;
        float var = fmaxf(sq / HDIM - mu * mu, 0.0f);
        float inv = rsqrtf(var + 1e-5f);
        for (int j = 0; j < HDIM; ++j) {
            float acc = b_ua[j];
            for (int k = 0; k < DDIM; ++k)
                acc += A[(size_t)row * DDIM + k] * w_ua[(size_t)k * HDIM + j];
            float x = gelu_exact(acc);
            float y = ((x - mu) * inv * g_ua[j] + be_ua[j]) * wn;
            atomicAdd(&g_agg[(size_t)rg * HDIM + j], y);
        }
    }
#endif
}

__device__ __forceinline__ float block_sum256(float v, float* sbuf) {
#pragma unroll
    for (int off = 1; off < 32; off <<= 1)
        v += __shfl_xor_sync(0xffffffffu, v, off);
    int w = threadIdx.x >> 5;
    if ((threadIdx.x & 31) == 0) sbuf[w] = v;
    __syncthreads();
    float t = 0.0f;
#pragma unroll
    for (int i = 0; i < 8; i++) t += sbuf[i];
    __syncthreads();
    return t;
}

__global__ __launch_bounds__(256) void region_up_kernel(
    const float* __restrict__ w_up, const float* __restrict__ b_up,
    const float* __restrict__ g_up, const float* __restrict__ be_up,
    const float* __restrict__ z_fused, const float* __restrict__ raw_rw,
    float* __restrict__ out_fused)
{
    __shared__ float a_s[HDIM];
    __shared__ float sbuf[8];
    int r = blockIdx.x, tid = threadIdx.x;
    a_s[tid] = g_agg[(size_t)r * HDIM + tid];
    __syncthreads();
    float acc0 = b_up[tid], acc1 = b_up[tid + 256];
    for (int k = 0; k < HDIM; k++) {
        float a = a_s[k];
        acc0 = fmaf(a, w_up[(size_t)k * DDIM + tid], acc0);
        acc1 = fmaf(a, w_up[(size_t)k * DDIM + tid + 256], acc1);
    }
    float x0 = gelu_exact(acc0), x1 = gelu_exact(acc1);
    float mu = block_sum256(x0 + x1, sbuf) * (1.0f / DDIM);
    float d0 = x0 - mu, d1 = x1 - mu;
    float var = block_sum256(d0 * d0 + d1 * d1, sbuf) * (1.0f / DDIM);
    float inv = rsqrtf(var + 1e-5f);
    float u0 = d0 * inv * g_up[tid] + be_up[tid];
    float u1 = d1 * inv * g_up[tid + 256] + be_up[tid + 256];
    bool present = g_cnt[r] > 0.0f;
    float zf0 = z_fused[(size_t)r * DDIM + tid];
    float zf1 = z_fused[(size_t)r * DDIM + tid + 256];
    float s0 = present ? u0 : zf0;
    float s1 = present ? u1 : zf1;
    size_t i0 = (size_t)r * DDIM + tid, i1 = i0 + 256;
    g_upd[i0] = s0;
    g_upd[i1] = s1;
    float h0 = tf32f(s0), h1 = tf32f(s1);
    g_upd_hi[i0] = h0; g_upd_lo[i0] = s0 - h0;
    g_upd_hi[i1] = h1; g_upd_lo[i1] = s1 - h1;
    float rw = 1.0f / (1.0f + expf(-__ldg(raw_rw)));
    out_fused[i0] = rw * s0 + (1.0f - rw) * zf0;
    out_fused[i1] = rw * s1 + (1.0f - rw) * zf1;
}

__global__ __launch_bounds__(256) void region_hb_kernel(
    const float* __restrict__ w_d1, const float* __restrict__ b_d1,
    const float* __restrict__ g_d1, const float* __restrict__ be_d1)
{
    __shared__ float z_s[DDIM];
    __shared__ float sbuf[8];
    int r = blockIdx.x, tid = threadIdx.x;
    z_s[tid] = g_upd[(size_t)r * DDIM + tid];
    z_s[tid + 256] = g_upd[(size_t)r * DDIM + tid + 256];
    __syncthreads();
    float acc = b_d1[tid];
    for (int k = 0; k < DDIM; k++)
        acc = fmaf(z_s[k], w_d1[(size_t)k * HDIM + tid], acc);
    float x = gelu_exact(acc);
    float mu = block_sum256(x, sbuf) * (1.0f / HDIM);
    float d = x - mu;
    float var = block_sum256(d * d, sbuf) * (1.0f / HDIM);
    float inv = rsqrtf(var + 1e-5f);
    g_hb[(size_t)r * HDIM + tid] = d * inv * g_d1[tid] + be_d1[tid];
}

__global__ __launch_bounds__(256) void region_bcast_kernel(
    const float* __restrict__ w_d2, const float* __restrict__ b_d2)
{
    __shared__ float h_s[HDIM];
    int r = blockIdx.x, tid = threadIdx.x;
    h_s[tid] = g_hb[(size_t)r * HDIM + tid];
    __syncthreads();
    float acc0 = b_d2[tid], acc1 = b_d2[tid + 256];
    for (int k = 0; k < HDIM; k++) {
        float h = h_s[k];
        acc0 = fmaf(h, w_d2[(size_t)k * DDIM + tid], acc0);
        acc1 = fmaf(h, w_d2[(size_t)k * DDIM + tid + 256], acc1);
    }
    g_bcast[(size_t)r * DDIM + tid] = acc0;
    g_bcast[(size_t)r * DDIM + tid + 256] = acc1;
}

extern "C" void kernel_launch(void* const* d_in, const int* in_sizes, int n_in,
                              void* d_out, int out_size) {
    const float* z_local = (const float*)d_in[0];
    const float* z_fused = (const float*)d_in[1];
    const int*   regions = (const int*)d_in[2];
    const float* protos  = (const float*)d_in[3];
    const float* temp    = (const float*)d_in[4];
    const float* raw_rw  = (const float*)d_in[5];
    const float* w_ua = (const float*)d_in[6];
    const float* b_ua = (const float*)d_in[7];
    const float* g_ua = (const float*)d_in[8];
    const float* be_ua = (const float*)d_in[9];
    const float* w_up = (const float*)d_in[10];
    const float* b_up = (const float*)d_in[11];
    const float* g_up = (const float*)d_in[12];
    const float* be_up = (const float*)d_in[13];
    const float* w_d1 = (const float*)d_in[14];
    const float* b_d1 = (const float*)d_in[15];
    const float* g_d1 = (const float*)d_in[16];
    const float* be_d1 = (const float*)d_in[17];
    const float* w_d2 = (const float*)d_in[18];
    const float* b_d2 = (const float*)d_in[19];

    float* out_local = (float*)d_out;
    float* out_fused = out_local + (size_t)NCELLS * DDIM;

    cudaFuncSetAttribute(pass_tc<0>, cudaFuncAttributeMaxDynamicSharedMemorySize, SM_TOTAL);
    cudaFuncSetAttribute(pass_tc<1>, cudaFuncAttributeMaxDynamicSharedMemorySize, SM_TOTAL);
    cudaFuncSetAttribute(h_agg_tc, cudaFuncAttributeMaxDynamicSharedMemorySize, HSM_TOTAL);

    init_kernel<<<(RREG * HDIM + 255) / 256, 256>>>();
    prep_kernel<<<(RREG * DDIM + 255) / 256, 256>>>(protos, w_ua);
    pass_tc<0><<<NCELLS / PT_M, 256, SM_TOTAL>>>(z_local, protos, regions, temp, raw_rw, nullptr);
    seg_sum_kernel<<<NCELLS / 256, 256>>>(regions);
    h_agg_tc<<<NCELLS / PT_M, 256, HSM_TOTAL>>>(z_local, w_ua, b_ua, g_ua, be_ua, regions);
    region_up_kernel<<<RREG, 256>>>(w_up, b_up, g_up, be_up, z_fused, raw_rw, out_fused);
    region_hb_kernel<<<RREG, 256>>>(w_d1, b_d1, g_d1, be_d1);
    region_bcast_kernel<<<RREG, 256>>>(w_d2, b_d2);
    pass_tc<1><<<NCELLS / PT_M, 256, SM_TOTAL>>>(z_local, nullptr, regions, temp, raw_rw, out_local);
}